// round 10
// baseline (speedup 1.0000x reference)
#include <cuda_runtime.h>
#include <cuda_fp16.h>
#include <math.h>
#include <stdint.h>

// B=8, T=2048, P=16, S=8, A=16, D=768, H=768, 3H=2304, 4D=3072

// ==================== scratch (device globals) ====================
__device__ float g_ps[8 * 16];
__device__ __align__(16) float g_h[8 * 768];
__device__ float g_segmean[128 * 768];
__device__ float g_vpo[128 * 768];
__device__ float g_para_h[128 * 768];
__device__ float g_para_o[128 * 768];
__device__ float g_qh[8 * 768];
__device__ float g_q[8 * 768];
__device__ float g_vpq[8 * 2304];
__device__ float g_zero[3072];
__device__ float g_base[8 * 3072];
__device__ __align__(128) float g_x[1024 * 768];
__device__ __align__(128) float g_gi[1024 * 2304];
__device__ __align__(128) float g_ghall[1024 * 2304];
__device__ __align__(16) float g_gh[8 * 2304];
__device__ float g_logpart[6 * 128];
__device__ int g_best[8];

// fp16 buffers (hi/lo split)
__device__ __align__(128) __half g_vid_hi[16384 * 768];
__device__ __align__(128) __half g_atx_hi[1024 * 768];
__device__ __align__(128) __half g_atx_lo[1024 * 768];
__device__ __align__(128) __half g_abt_hi[1024 * 768];
__device__ __align__(128) __half g_abt_lo[1024 * 768];
__device__ __align__(128) __half g_wih_hi[2304 * 768];
__device__ __align__(128) __half g_wih_lo[2304 * 768];
__device__ __align__(128) __half g_whh_hi[2304 * 768];
__device__ __align__(128) __half g_whh_lo[2304 * 768];
__device__ __align__(128) __half g_mvw1t_hi[768 * 768];
__device__ __align__(128) __half g_mvw1t_lo[768 * 768];
__device__ __align__(128) __half g_mvw2t_hi[768 * 768];
__device__ __align__(128) __half g_mvw2t_lo[768 * 768];
__device__ __align__(128) __half g_mtw1t_hi[768 * 768];
__device__ __align__(128) __half g_mtw1t_lo[768 * 768];
__device__ __align__(128) __half g_mtw2t_hi[768 * 768];
__device__ __align__(128) __half g_mtw2t_lo[768 * 768];
__device__ __align__(128) __half g_mpw1rt_hi[3072 * 1536];
__device__ __align__(128) __half g_mpw1rt_lo[3072 * 1536];
__device__ __align__(128) __half g_mpw2t_hi[768 * 3072];
__device__ __align__(128) __half g_mpw2t_lo[768 * 3072];
__device__ __align__(128) __half g_tha_hi[1024 * 768];
__device__ __align__(128) __half g_tha_lo[1024 * 768];
__device__ __align__(128) __half g_thb_hi[1024 * 768];
__device__ __align__(128) __half g_thb_lo[1024 * 768];
__device__ __align__(128) __half g_inpAB_hi[1024 * 1536];
__device__ __align__(128) __half g_inpAB_lo[1024 * 1536];
__device__ __align__(128) __half g_preh_hi[1024 * 3072];
__device__ __align__(128) __half g_preh_lo[1024 * 3072];
__device__ __align__(128) __half g_x_hi[1024 * 768];
__device__ __align__(128) __half g_x_lo[1024 * 768];

// ==================== mma.sync helpers ====================
__device__ __forceinline__ void ldm_x4(uint32_t f[4], uint32_t addr) {
    asm volatile("ldmatrix.sync.aligned.m8n8.x4.shared.b16 {%0,%1,%2,%3}, [%4];"
                 : "=r"(f[0]), "=r"(f[1]), "=r"(f[2]), "=r"(f[3]) : "r"(addr));
}
__device__ __forceinline__ void mma16816(float* c, const uint32_t a[4],
                                         uint32_t b0, uint32_t b1) {
    asm volatile(
        "mma.sync.aligned.m16n8k16.row.col.f32.f16.f16.f32 "
        "{%0,%1,%2,%3}, {%4,%5,%6,%7}, {%8,%9}, {%0,%1,%2,%3};"
        : "+f"(c[0]), "+f"(c[1]), "+f"(c[2]), "+f"(c[3])
        : "r"(a[0]), "r"(a[1]), "r"(a[2]), "r"(a[3]), "r"(b0), "r"(b1));
}
#define CP_ASYNC16(dst, src) \
    asm volatile("cp.async.cg.shared.global [%0], [%1], 16;" :: "r"(dst), "l"(src))
#define CP_COMMIT() asm volatile("cp.async.commit_group;")
#define CP_WAIT(n)  asm volatile("cp.async.wait_group %0;" :: "n"(n))

struct Ops {
    const __half *Ahi, *Alo, *Bhi, *Blo;
    const float* bias;
    const float* base;
    float* C;
    __half *Chi, *Clo;
    int ldc;
};
struct Ops2 { Ops o[2]; };

// ==================== HMMA GEMM (proven core) ====================
template <int MT, int NPROD, bool RELU, bool SPLITOUT, bool F32OUT, bool BADD, bool SEG>
__global__ void __launch_bounds__(256, 2) k_hmma(Ops2 ops, int M, int N, int K)
{
    const Ops op = ops.o[blockIdx.z];
    extern __shared__ __align__(128) char smem[];
    const uint32_t s_base = (uint32_t)__cvta_generic_to_shared(smem);
    constexpr int STAGE_BYTES = (MT + 128) * 128;
    constexpr int MI = MT / 32;
    constexpr int KADV = (NPROD == 3) ? 32 : 64;
    constexpr int ACP = MT * 8;

    const int tid = threadIdx.x;
    const int wid = tid >> 5, lane = tid & 31;
    const int wm = wid & 1, wn = wid >> 1;
    const int row0 = blockIdx.y * MT;
    const int col0 = blockIdx.x * 128;
    const int NC = K / KADV;

    float acc[MI][4][4];
    #pragma unroll
    for (int i = 0; i < MI; i++)
        #pragma unroll
        for (int j = 0; j < 4; j++)
            #pragma unroll
            for (int r = 0; r < 4; r++) acc[i][j][r] = 0.f;

    auto load_stage = [&](int c) {
        const int k0 = c * KADV;
        const uint32_t sb = s_base + (uint32_t)((c & 1) * STAGE_BYTES);
        #pragma unroll
        for (int i = tid; i < ACP + 1024; i += 256) {
            const bool isA = i < ACP;
            const int e = isA ? i : i - ACP;
            const int row = e >> 3, ch = e & 7;
            const int grow = (isA ? row0 : col0) + row;
            const __half* src;
            if (NPROD == 3) {
                const int o2 = ch >> 2, kc = ch & 3;
                const __half* base = isA ? (o2 ? op.Alo : op.Ahi) : (o2 ? op.Blo : op.Bhi);
                src = base + (size_t)grow * K + k0 + kc * 8;
            } else {
                src = (isA ? op.Ahi : op.Bhi) + (size_t)grow * K + k0 + ch * 8;
            }
            const uint32_t dst = sb + (uint32_t)((isA ? 0 : MT * 128)
                               + row * 128 + ((ch ^ (row & 7)) << 4));
            CP_ASYNC16(dst, src);
        }
        CP_COMMIT();
    };

    load_stage(0);

    for (int c = 0; c < NC; c++) {
        if (c + 1 < NC) { load_stage(c + 1); CP_WAIT(1); }
        else            { CP_WAIT(0); }
        __syncthreads();

        const uint32_t sA = s_base + (uint32_t)((c & 1) * STAGE_BYTES);
        const uint32_t sB = sA + MT * 128;
        constexpr int NK = (NPROD == 3) ? 2 : 4;

        #pragma unroll
        for (int s = 0; s < NK; s++) {
            uint32_t ah[MI][4], bh[2][4];
            #pragma unroll
            for (int mt = 0; mt < MI; mt++) {
                const int row = wm * (MT / 2) + mt * 16 + (lane & 15);
                const int ch = s * 2 + (lane >> 4);
                ldm_x4(ah[mt], sA + row * 128 + ((ch ^ (row & 7)) << 4));
            }
            #pragma unroll
            for (int ntp = 0; ntp < 2; ntp++) {
                const int row = wn * 32 + ntp * 16 + ((lane >> 4) << 3) + (lane & 7);
                const int ch = s * 2 + ((lane >> 3) & 1);
                ldm_x4(bh[ntp], sB + row * 128 + ((ch ^ (row & 7)) << 4));
            }
            if (NPROD == 3) {
                uint32_t al[MI][4], bl[2][4];
                #pragma unroll
                for (int mt = 0; mt < MI; mt++) {
                    const int row = wm * (MT / 2) + mt * 16 + (lane & 15);
                    const int ch = 4 + s * 2 + (lane >> 4);
                    ldm_x4(al[mt], sA + row * 128 + ((ch ^ (row & 7)) << 4));
                }
                #pragma unroll
                for (int ntp = 0; ntp < 2; ntp++) {
                    const int row = wn * 32 + ntp * 16 + ((lane >> 4) << 3) + (lane & 7);
                    const int ch = 4 + s * 2 + ((lane >> 3) & 1);
                    ldm_x4(bl[ntp], sB + row * 128 + ((ch ^ (row & 7)) << 4));
                }
                #pragma unroll
                for (int mt = 0; mt < MI; mt++)
                    #pragma unroll
                    for (int nt = 0; nt < 4; nt++) {
                        const int p = nt >> 1, q = (nt & 1) * 2;
                        mma16816(acc[mt][nt], ah[mt], bh[p][q], bh[p][q + 1]);
                        mma16816(acc[mt][nt], ah[mt], bl[p][q], bl[p][q + 1]);
                        mma16816(acc[mt][nt], al[mt], bh[p][q], bh[p][q + 1]);
                    }
            } else {
                #pragma unroll
                for (int mt = 0; mt < MI; mt++)
                    #pragma unroll
                    for (int nt = 0; nt < 4; nt++) {
                        const int p = nt >> 1, q = (nt & 1) * 2;
                        mma16816(acc[mt][nt], ah[mt], bh[p][q], bh[p][q + 1]);
                    }
            }
        }
        __syncthreads();
    }

    float csum[4][2];
    if (SEG) {
        #pragma unroll
        for (int nt = 0; nt < 4; nt++) { csum[nt][0] = 0.f; csum[nt][1] = 0.f; }
    }
    #pragma unroll
    for (int mt = 0; mt < MI; mt++) {
        #pragma unroll
        for (int nt = 0; nt < 4; nt++) {
            const int col = col0 + wn * 32 + nt * 8 + (lane & 3) * 2;
            const float2 bv = *reinterpret_cast<const float2*>(op.bias + col);
            #pragma unroll
            for (int half = 0; half < 2; half++) {
                const int grow = row0 + wm * (MT / 2) + mt * 16 + (lane >> 2) + half * 8;
                float v0 = acc[mt][nt][half * 2 + 0] + bv.x;
                float v1 = acc[mt][nt][half * 2 + 1] + bv.y;
                if (BADD) {
                    const float2 bsv = *reinterpret_cast<const float2*>(
                        op.base + (size_t)(grow >> 7) * 3072 + col);
                    v0 += bsv.x; v1 += bsv.y;
                }
                if (RELU) { v0 = fmaxf(v0, 0.f); v1 = fmaxf(v1, 0.f); }
                if (SEG) { csum[nt][0] += v0; csum[nt][1] += v1; }
                if (F32OUT)
                    *reinterpret_cast<float2*>(op.C + (size_t)grow * op.ldc + col) =
                        make_float2(v0, v1);
                if (SPLITOUT) {
                    const __half h0 = __float2half_rn(v0);
                    const __half h1 = __float2half_rn(v1);
                    const __half l0 = __float2half_rn(v0 - __half2float(h0));
                    const __half l1 = __float2half_rn(v1 - __half2float(h1));
                    *reinterpret_cast<__half2*>(op.Chi + (size_t)grow * op.ldc + col) =
                        make_half2(h0, h1);
                    *reinterpret_cast<__half2*>(op.Clo + (size_t)grow * op.ldc + col) =
                        make_half2(l0, l1);
                }
            }
        }
    }
    if (SEG) {
        #pragma unroll
        for (int o = 4; o <= 16; o <<= 1)
            #pragma unroll
            for (int nt = 0; nt < 4; nt++) {
                csum[nt][0] += __shfl_xor_sync(0xffffffffu, csum[nt][0], o);
                csum[nt][1] += __shfl_xor_sync(0xffffffffu, csum[nt][1], o);
            }
        float* scol = reinterpret_cast<float*>(smem);
        if (tid < 128) scol[tid] = 0.f;
        __syncthreads();
        if ((lane >> 2) == 0) {
            #pragma unroll
            for (int nt = 0; nt < 4; nt++) {
                atomicAdd(&scol[wn * 32 + nt * 8 + (lane & 3) * 2 + 0], csum[nt][0]);
                atomicAdd(&scol[wn * 32 + nt * 8 + (lane & 3) * 2 + 1], csum[nt][1]);
            }
        }
        __syncthreads();
        if (tid < 128)
            op.C[(size_t)blockIdx.y * 768 + col0 + tid] = scol[tid] * (1.f / 128.f);
    }
}

// ==================== conversion kernels (batched) ====================
__global__ void k_half(const float* __restrict__ in, __half* __restrict__ hi, int n4) {
    int i = blockIdx.x * 256 + threadIdx.x;
    if (i >= n4) return;
    float4 v = reinterpret_cast<const float4*>(in)[i];
    reinterpret_cast<__half2*>(hi)[i * 2 + 0] =
        make_half2(__float2half_rn(v.x), __float2half_rn(v.y));
    reinterpret_cast<__half2*>(hi)[i * 2 + 1] =
        make_half2(__float2half_rn(v.z), __float2half_rn(v.w));
}

struct Split2 { const float* in[2]; __half* hi[2]; __half* lo[2]; int n4[2]; };
__global__ void k_split2(Split2 p) {
    const int z = blockIdx.z;
    int i = blockIdx.x * 256 + threadIdx.x;
    if (i >= p.n4[z]) return;
    float4 v = reinterpret_cast<const float4*>(p.in[z])[i];
    __half h0 = __float2half_rn(v.x), h1 = __float2half_rn(v.y);
    __half h2 = __float2half_rn(v.z), h3 = __float2half_rn(v.w);
    __half l0 = __float2half_rn(v.x - __half2float(h0));
    __half l1 = __float2half_rn(v.y - __half2float(h1));
    __half l2 = __float2half_rn(v.z - __half2float(h2));
    __half l3 = __float2half_rn(v.w - __half2float(h3));
    reinterpret_cast<__half2*>(p.hi[z])[i * 2 + 0] = make_half2(h0, h1);
    reinterpret_cast<__half2*>(p.hi[z])[i * 2 + 1] = make_half2(h2, h3);
    reinterpret_cast<__half2*>(p.lo[z])[i * 2 + 0] = make_half2(l0, l1);
    reinterpret_cast<__half2*>(p.lo[z])[i * 2 + 1] = make_half2(l2, l3);
}

__global__ void k_splitT(const float* __restrict__ W, __half* __restrict__ hi,
                         __half* __restrict__ lo, int K, int N) {
    __shared__ float t[32][33];
    const int kb = blockIdx.y * 32, nb = blockIdx.x * 32;
    const int tx = threadIdx.x & 31, ty = threadIdx.x >> 5;
    #pragma unroll
    for (int r = ty; r < 32; r += 8)
        t[r][tx] = W[(size_t)(kb + r) * N + nb + tx];
    __syncthreads();
    #pragma unroll
    for (int r = ty; r < 32; r += 8) {
        float v = t[tx][r];
        __half h = __float2half_rn(v);
        __half l = __float2half_rn(v - __half2float(h));
        size_t o = (size_t)(nb + r) * K + kb + tx;
        hi[o] = h;
        lo[o] = l;
    }
}

struct ST4 { const float* W[4]; __half* hi[4]; __half* lo[4]; };
__global__ void k_splitT4(ST4 p) {   // all 768x768
    const int z = blockIdx.z;
    __shared__ float t[32][33];
    const int kb = blockIdx.y * 32, nb = blockIdx.x * 32;
    const int tx = threadIdx.x & 31, ty = threadIdx.x >> 5;
    #pragma unroll
    for (int r = ty; r < 32; r += 8)
        t[r][tx] = p.W[z][(size_t)(kb + r) * 768 + nb + tx];
    __syncthreads();
    #pragma unroll
    for (int r = ty; r < 32; r += 8) {
        float v = t[tx][r];
        __half h = __float2half_rn(v);
        __half l = __float2half_rn(v - __half2float(h));
        size_t o = (size_t)(nb + r) * 768 + kb + tx;
        p.hi[z][o] = h;
        p.lo[z][o] = l;
    }
}

// ==================== fp32 helper kernels ====================
__global__ void k_softmax_init(const float* __restrict__ scores,
                               const float* __restrict__ state0) {
    int tid = threadIdx.x;
    int warp = tid >> 5, lane = tid & 31;
    if (warp < 8) {
        float v = (lane < 16) ? scores[warp * 16 + lane] : -1e30f;
        float m = v;
        #pragma unroll
        for (int o = 16; o > 0; o >>= 1) m = fmaxf(m, __shfl_xor_sync(0xffffffffu, m, o));
        float e = (lane < 16) ? expf(v - m) : 0.f;
        float s = e;
        #pragma unroll
        for (int o = 16; o > 0; o >>= 1) s += __shfl_xor_sync(0xffffffffu, s, o);
        if (lane < 16) g_ps[warp * 16 + lane] = e / s;
    }
    for (int i = tid; i < 8 * 768; i += blockDim.x) g_h[i] = state0[i % 768];
    for (int i = tid; i < 3072; i += blockDim.x) g_zero[i] = 0.f;
}

// plain fp32 GEMM 16x128 tile (proven); used for base
template <bool RELU>
__global__ void __launch_bounds__(256) k_gemm16(
    const float* __restrict__ A, const float* __restrict__ W,
    const float* __restrict__ bias, float* __restrict__ C,
    int M, int N, int K) {
    __shared__ __align__(16) float As[32][16];
    __shared__ __align__(16) float Ws[32][128];
    const int tid = threadIdx.x;
    const int row0 = blockIdx.y * 16;
    const int col0 = blockIdx.x * 128;
    const int row = tid >> 4;
    const int cg = tid & 15;
    float acc[8];
    #pragma unroll
    for (int j = 0; j < 8; j++) acc[j] = 0.f;
    for (int k0 = 0; k0 < K; k0 += 32) {
        if (tid < 128) {
            int ar = tid >> 3, ac = (tid & 7) * 4;
            float4 av = make_float4(0.f, 0.f, 0.f, 0.f);
            int gr = row0 + ar;
            if (gr < M) av = *reinterpret_cast<const float4*>(A + (size_t)gr * K + k0 + ac);
            As[ac + 0][ar] = av.x; As[ac + 1][ar] = av.y;
            As[ac + 2][ar] = av.z; As[ac + 3][ar] = av.w;
        }
        #pragma unroll
        for (int j = 0; j < 4; j++) {
            int wr = (tid >> 5) + j * 8;
            int wc = (tid & 31) * 4;
            float4 wv = *reinterpret_cast<const float4*>(W + (size_t)(k0 + wr) * N + col0 + wc);
            *reinterpret_cast<float4*>(&Ws[wr][wc]) = wv;
        }
        __syncthreads();
        #pragma unroll
        for (int k = 0; k < 32; k++) {
            float a = As[k][row];
            float4 b0 = *reinterpret_cast<const float4*>(&Ws[k][cg * 4]);
            float4 b1 = *reinterpret_cast<const float4*>(&Ws[k][64 + cg * 4]);
            acc[0] = fmaf(a, b0.x, acc[0]); acc[1] = fmaf(a, b0.y, acc[1]);
            acc[2] = fmaf(a, b0.z, acc[2]); acc[3] = fmaf(a, b0.w, acc[3]);
            acc[4] = fmaf(a, b1.x, acc[4]); acc[5] = fmaf(a, b1.y, acc[5]);
            acc[6] = fmaf(a, b1.z, acc[6]); acc[7] = fmaf(a, b1.w, acc[7]);
        }
        __syncthreads();
    }
    int r = row0 + row;
    if (r < M) {
        float4 bv0 = *reinterpret_cast<const float4*>(bias + col0 + cg * 4);
        float4 bv1 = *reinterpret_cast<const float4*>(bias + col0 + 64 + cg * 4);
        float o[8];
        o[0] = acc[0] + bv0.x; o[1] = acc[1] + bv0.y;
        o[2] = acc[2] + bv0.z; o[3] = acc[3] + bv0.w;
        o[4] = acc[4] + bv1.x; o[5] = acc[5] + bv1.y;
        o[6] = acc[6] + bv1.z; o[7] = acc[7] + bv1.w;
        if (RELU) {
            #pragma unroll
            for (int j = 0; j < 8; j++) o[j] = fmaxf(o[j], 0.f);
        }
        *reinterpret_cast<float4*>(C + (size_t)r * N + col0 + cg * 4) =
            make_float4(o[0], o[1], o[2], o[3]);
        *reinterpret_cast<float4*>(C + (size_t)r * N + col0 + 64 + cg * 4) =
            make_float4(o[4], o[5], o[6], o[7]);
    }
}

// z-batched variant: per-z operand set (N=768, K=768 fixed here)
struct G16 { const float* A; const float* W; const float* bias; float* C; int M; };
struct G16x3 { G16 g[3]; };
template <bool RELU>
__global__ void __launch_bounds__(256) k_gemm16z(G16x3 p, int N, int K) {
    const G16 gz = p.g[blockIdx.z];
    const int row0 = blockIdx.y * 16;
    if (row0 >= gz.M) return;
    __shared__ __align__(16) float As[32][16];
    __shared__ __align__(16) float Ws[32][128];
    const int tid = threadIdx.x;
    const int col0 = blockIdx.x * 128;
    const int row = tid >> 4;
    const int cg = tid & 15;
    float acc[8];
    #pragma unroll
    for (int j = 0; j < 8; j++) acc[j] = 0.f;
    for (int k0 = 0; k0 < K; k0 += 32) {
        if (tid < 128) {
            int ar = tid >> 3, ac = (tid & 7) * 4;
            float4 av = make_float4(0.f, 0.f, 0.f, 0.f);
            int gr = row0 + ar;
            if (gr < gz.M) av = *reinterpret_cast<const float4*>(gz.A + (size_t)gr * K + k0 + ac);
            As[ac + 0][ar] = av.x; As[ac + 1][ar] = av.y;
            As[ac + 2][ar] = av.z; As[ac + 3][ar] = av.w;
        }
        #pragma unroll
        for (int j = 0; j < 4; j++) {
            int wr = (tid >> 5) + j * 8;
            int wc = (tid & 31) * 4;
            float4 wv = *reinterpret_cast<const float4*>(gz.W + (size_t)(k0 + wr) * N + col0 + wc);
            *reinterpret_cast<float4*>(&Ws[wr][wc]) = wv;
        }
        __syncthreads();
        #pragma unroll
        for (int k = 0; k < 32; k++) {
            float a = As[k][row];
            float4 b0 = *reinterpret_cast<const float4*>(&Ws[k][cg * 4]);
            float4 b1 = *reinterpret_cast<const float4*>(&Ws[k][64 + cg * 4]);
            acc[0] = fmaf(a, b0.x, acc[0]); acc[1] = fmaf(a, b0.y, acc[1]);
            acc[2] = fmaf(a, b0.z, acc[2]); acc[3] = fmaf(a, b0.w, acc[3]);
            acc[4] = fmaf(a, b1.x, acc[4]); acc[5] = fmaf(a, b1.y, acc[5]);
            acc[6] = fmaf(a, b1.z, acc[6]); acc[7] = fmaf(a, b1.w, acc[7]);
        }
        __syncthreads();
    }
    int r = row0 + row;
    if (r < gz.M) {
        float4 bv0 = *reinterpret_cast<const float4*>(gz.bias + col0 + cg * 4);
        float4 bv1 = *reinterpret_cast<const float4*>(gz.bias + col0 + 64 + cg * 4);
        float o[8];
        o[0] = acc[0] + bv0.x; o[1] = acc[1] + bv0.y;
        o[2] = acc[2] + bv0.z; o[3] = acc[3] + bv0.w;
        o[4] = acc[4] + bv1.x; o[5] = acc[5] + bv1.y;
        o[6] = acc[6] + bv1.z; o[7] = acc[7] + bv1.w;
        if (RELU) {
            #pragma unroll
            for (int j = 0; j < 8; j++) o[j] = fmaxf(o[j], 0.f);
        }
        *reinterpret_cast<float4*>(gz.C + (size_t)r * N + col0 + cg * 4) =
            make_float4(o[0], o[1], o[2], o[3]);
        *reinterpret_cast<float4*>(gz.C + (size_t)r * N + col0 + 64 + cg * 4) =
            make_float4(o[4], o[5], o[6], o[7]);
    }
}

// vpq assembly: z0: vp = ps@vpo -> vpq[0:768]; z1: pr = ps@para_o -> vpq[768:1536];
// z2: copy q -> vpq[1536:2304]
__global__ void k_wsum3() {
    const int z = blockIdx.z;
    const int b = blockIdx.y;
    const int d = blockIdx.x * 256 + threadIdx.x;
    if (z == 2) {
        g_vpq[b * 2304 + 1536 + d] = g_q[b * 768 + d];
        return;
    }
    const float* in = (z == 0) ? g_vpo : g_para_o;
    float acc = 0.f;
    #pragma unroll
    for (int p = 0; p < 16; p++)
        acc = fmaf(g_ps[b * 16 + p], in[(size_t)(b * 16 + p) * 768 + d], acc);
    g_vpq[b * 2304 + z * 768 + d] = acc;
}

// gh for step 0: gh[b] = whh @ state0-rows + bhh (exact fp32)
__global__ void __launch_bounds__(128) k_gh(const float* __restrict__ whh,
                                            const float* __restrict__ bhh) {
    __shared__ float hs[8 * 768];
    for (int i = threadIdx.x; i < 8 * 768; i += 128) hs[i] = g_h[i];
    __syncthreads();
    int n = blockIdx.x * 128 + threadIdx.x;
    float bv = bhh[n];
    float acc[8];
    #pragma unroll
    for (int b = 0; b < 8; b++) acc[b] = bv;
    const float4* wr = reinterpret_cast<const float4*>(whh + (size_t)n * 768);
    #pragma unroll 4
    for (int k4 = 0; k4 < 192; k4++) {
        float4 w = wr[k4];
        int kb = k4 * 4;
        #pragma unroll
        for (int b = 0; b < 8; b++) {
            const float* hb = hs + b * 768 + kb;
            acc[b] = fmaf(w.x, hb[0], fmaf(w.y, hb[1], fmaf(w.z, hb[2], fmaf(w.w, hb[3], acc[b]))));
        }
    }
    #pragma unroll
    for (int b = 0; b < 8; b++) g_gh[b * 2304 + n] = acc[b];
}

// ==================== fused scan step 1: GRU + proj-L1 tile + partial logits ====
// grid (6, 8): y = 16-row group, x = 128-col group. Dynamic smem:
// states tile 16x768 (48KB) + Ws 32x128 (16KB) = 64KB.
__global__ void __launch_bounds__(256) k_step1(
    int s, const float* __restrict__ w1, const float* __restrict__ b1,
    const float* __restrict__ w2)
{
    extern __shared__ float dsm[];
    float* st = dsm;                 // [16][768]
    float* Ws = dsm + 16 * 768;      // [32][128]
    const int tid = threadIdx.x;
    const int row0 = blockIdx.y * 16;
    const int col0 = blockIdx.x * 128;

    // GRU elementwise for this CTA's 16 rows (recomputed per x-block; cheap, L2-hot)
    for (int idx = tid; idx < 16 * 768; idx += 256) {
        const int rr = idx / 768, hh = idx - rr * 768;
        const int r = row0 + rr;
        const int b = r >> 4, a = r & 15;
        const size_t gib = (size_t)((b * 8 + s) * 16 + a) * 2304;
        const float* ghrow;
        const float* hprev;
        if (s == 0) {
            ghrow = g_gh + b * 2304;
            hprev = g_h + b * 768;
        } else {
            const int prev = (b * 8 + (s - 1)) * 16 + g_best[b];
            ghrow = g_ghall + (size_t)prev * 2304;
            hprev = g_x + (size_t)prev * 768;
        }
        const float ir = g_gi[gib + hh];
        const float iz = g_gi[gib + 768 + hh];
        const float in_ = g_gi[gib + 1536 + hh];
        const float rr_ = 1.f / (1.f + expf(-(ir + ghrow[hh])));
        const float zz = 1.f / (1.f + expf(-(iz + ghrow[768 + hh])));
        const float nn = tanhf(in_ + rr_ * ghrow[1536 + hh]);
        st[rr * 768 + hh] = (1.f - zz) * nn + zz * hprev[hh];
    }
    __syncthreads();

    // proj L1 tile 16x128 (fp32, k_gemm16 inner structure, A from smem)
    const int row = tid >> 4, cg = tid & 15;
    float acc[8];
    #pragma unroll
    for (int j = 0; j < 8; j++) acc[j] = 0.f;
    for (int k0 = 0; k0 < 768; k0 += 32) {
        #pragma unroll
        for (int j = 0; j < 4; j++) {
            const int wr = (tid >> 5) + j * 8;
            const int wc = (tid & 31) * 4;
            *reinterpret_cast<float4*>(&Ws[wr * 128 + wc]) =
                *reinterpret_cast<const float4*>(w1 + (size_t)(k0 + wr) * 768 + col0 + wc);
        }
        __syncthreads();
        #pragma unroll
        for (int k = 0; k < 32; k++) {
            const float a = st[row * 768 + k0 + k];
            const float4 b0 = *reinterpret_cast<const float4*>(&Ws[k * 128 + cg * 4]);
            const float4 b1v = *reinterpret_cast<const float4*>(&Ws[k * 128 + 64 + cg * 4]);
            acc[0] = fmaf(a, b0.x, acc[0]); acc[1] = fmaf(a, b0.y, acc[1]);
            acc[2] = fmaf(a, b0.z, acc[2]); acc[3] = fmaf(a, b0.w, acc[3]);
            acc[4] = fmaf(a, b1v.x, acc[4]); acc[5] = fmaf(a, b1v.y, acc[5]);
            acc[6] = fmaf(a, b1v.z, acc[6]); acc[7] = fmaf(a, b1v.w, acc[7]);
        }
        __syncthreads();
    }

    // bias + relu + partial logit dot over this CTA's 128 cols
    const float4 bv0 = *reinterpret_cast<const float4*>(b1 + col0 + cg * 4);
    const float4 bv1 = *reinterpret_cast<const float4*>(b1 + col0 + 64 + cg * 4);
    const float4 w20 = *reinterpret_cast<const float4*>(w2 + col0 + cg * 4);
    const float4 w21 = *reinterpret_cast<const float4*>(w2 + col0 + 64 + cg * 4);
    float part = 0.f;
    part += fmaxf(acc[0] + bv0.x, 0.f) * w20.x;
    part += fmaxf(acc[1] + bv0.y, 0.f) * w20.y;
    part += fmaxf(acc[2] + bv0.z, 0.f) * w20.z;
    part += fmaxf(acc[3] + bv0.w, 0.f) * w20.w;
    part += fmaxf(acc[4] + bv1.x, 0.f) * w21.x;
    part += fmaxf(acc[5] + bv1.y, 0.f) * w21.y;
    part += fmaxf(acc[6] + bv1.z, 0.f) * w21.z;
    part += fmaxf(acc[7] + bv1.w, 0.f) * w21.w;
    // reduce across the 16 cg-lanes of this row (offsets < 16 stay in-group)
    #pragma unroll
    for (int off = 1; off < 16; off <<= 1)
        part += __shfl_xor_sync(0xffffffffu, part, off);
    if (cg == 0)
        g_logpart[blockIdx.x * 128 + row0 + row] = part;
}

// scan step 2: deterministic logit sum (fixed order), output, first-max argmax
__global__ void k_step2(const float* __restrict__ b2, float* __restrict__ out, int s) {
    const int b = blockIdx.x;
    const int lane = threadIdx.x;  // 32 threads
    float val = -1e30f;
    int idx = 1000;
    if (lane < 16) {
        float lg = b2[0];
        #pragma unroll
        for (int x = 0; x < 6; x++) lg += g_logpart[x * 128 + b * 16 + lane];
        out[(b * 8 + s) * 16 + lane] = lg;
        val = lg;
        idx = lane;
    }
    #pragma unroll
    for (int off = 8; off > 0; off >>= 1) {
        const float oval = __shfl_down_sync(0xffffffffu, val, off);
        const int oidx = __shfl_down_sync(0xffffffffu, idx, off);
        if (oval > val || (oval == val && oidx < idx)) { val = oval; idx = oidx; }
    }
    if (lane == 0) g_best[b] = idx;
}

// ==================== host ====================
#define GETSYM(p, s) cudaGetSymbolAddress((void**)&(p), s)

extern "C" void kernel_launch(void* const* d_in, const int* in_sizes, int n_in,
                              void* d_out, int out_size) {
    (void)in_sizes; (void)n_in; (void)out_size;
    const float* video     = (const float*)d_in[0];
    const float* para      = (const float*)d_in[1];
    const float* question  = (const float*)d_in[2];
    const float* pscore    = (const float*)d_in[3];
    const float* a_texts   = (const float*)d_in[4];
    const float* a_buttons = (const float*)d_in[5];
    const float* mv_w1 = (const float*)d_in[6],  *mv_b1 = (const float*)d_in[7];
    const float* mv_w2 = (const float*)d_in[8],  *mv_b2 = (const float*)d_in[9];
    const float* mt_w1 = (const float*)d_in[10], *mt_b1 = (const float*)d_in[11];
    const float* mt_w2 = (const float*)d_in[12], *mt_b2 = (const float*)d_in[13];
    const float* mp_w1 = (const float*)d_in[14], *mp_b1 = (const float*)d_in[15];
    const float* mp_w2 = (const float*)d_in[16], *mp_b2 = (const float*)d_in[17];
    const float* wih   = (const float*)d_in[18], *bih   = (const float*)d_in[19];
    const float* whh   = (const float*)d_in[20], *bhh   = (const float*)d_in[21];
    const float* pr_w1 = (const float*)d_in[22], *pr_b1 = (const float*)d_in[23];
    const float* pr_w2 = (const float*)d_in[24], *pr_b2 = (const float*)d_in[25];
    const float* state0 = (const float*)d_in[26];
    float* out = (float*)d_out;

    float *pseg, *pvpo, *pparah, *pparao, *pqh, *pq;
    float *pvpq, *pzero, *pbase, *px, *pgi, *pghall;
    GETSYM(pseg, g_segmean); GETSYM(pvpo, g_vpo);
    GETSYM(pparah, g_para_h); GETSYM(pparao, g_para_o);
    GETSYM(pqh, g_qh); GETSYM(pq, g_q);
    GETSYM(pvpq, g_vpq); GETSYM(pzero, g_zero); GETSYM(pbase, g_base);
    GETSYM(px, g_x); GETSYM(pgi, g_gi); GETSYM(pghall, g_ghall);

    __half *vid_hi, *atx_hi, *atx_lo, *abt_hi, *abt_lo;
    __half *wih_hi, *wih_lo, *whh_hi, *whh_lo;
    __half *mvw1t_hi, *mvw1t_lo, *mvw2t_hi, *mvw2t_lo, *mtw1t_hi, *mtw1t_lo;
    __half *mtw2t_hi, *mtw2t_lo, *mpw1rt_hi, *mpw1rt_lo, *mpw2t_hi, *mpw2t_lo;
    __half *tha_hi, *tha_lo, *thb_hi, *thb_lo, *inpAB_hi, *inpAB_lo;
    __half *preh_hi, *preh_lo, *x_hi, *x_lo;
    GETSYM(vid_hi, g_vid_hi);
    GETSYM(atx_hi, g_atx_hi); GETSYM(atx_lo, g_atx_lo);
    GETSYM(abt_hi, g_abt_hi); GETSYM(abt_lo, g_abt_lo);
    GETSYM(wih_hi, g_wih_hi); GETSYM(wih_lo, g_wih_lo);
    GETSYM(whh_hi, g_whh_hi); GETSYM(whh_lo, g_whh_lo);
    GETSYM(mvw1t_hi, g_mvw1t_hi); GETSYM(mvw1t_lo, g_mvw1t_lo);
    GETSYM(mvw2t_hi, g_mvw2t_hi); GETSYM(mvw2t_lo, g_mvw2t_lo);
    GETSYM(mtw1t_hi, g_mtw1t_hi); GETSYM(mtw1t_lo, g_mtw1t_lo);
    GETSYM(mtw2t_hi, g_mtw2t_hi); GETSYM(mtw2t_lo, g_mtw2t_lo);
    GETSYM(mpw1rt_hi, g_mpw1rt_hi); GETSYM(mpw1rt_lo, g_mpw1rt_lo);
    GETSYM(mpw2t_hi, g_mpw2t_hi); GETSYM(mpw2t_lo, g_mpw2t_lo);
    GETSYM(tha_hi, g_tha_hi); GETSYM(tha_lo, g_tha_lo);
    GETSYM(thb_hi, g_thb_hi); GETSYM(thb_lo, g_thb_lo);
    GETSYM(inpAB_hi, g_inpAB_hi); GETSYM(inpAB_lo, g_inpAB_lo);
    GETSYM(preh_hi, g_preh_hi); GETSYM(preh_lo, g_preh_lo);
    GETSYM(x_hi, g_x_hi); GETSYM(x_lo, g_x_lo);

    constexpr int SM128 = (128 + 128) * 128 * 2;  // 65536
    constexpr int SM64  = (64 + 128) * 128 * 2;   // 49152
    constexpr int SM32  = (32 + 128) * 128 * 2;   // 40960
    constexpr int SMSTEP = 16 * 768 * 4 + 32 * 128 * 4;  // 65536
    cudaFuncSetAttribute(k_hmma<128, 1, true,  false, false, false, true >, cudaFuncAttributeMaxDynamicSharedMemorySize, SM128);
    cudaFuncSetAttribute(k_hmma<32,  3, true,  true,  false, false, false>, cudaFuncAttributeMaxDynamicSharedMemorySize, SM32);
    cudaFuncSetAttribute(k_hmma<32,  3, false, true,  false, false, false>, cudaFuncAttributeMaxDynamicSharedMemorySize, SM32);
    cudaFuncSetAttribute(k_hmma<64,  3, true,  true,  false, true,  false>, cudaFuncAttributeMaxDynamicSharedMemorySize, SM64);
    cudaFuncSetAttribute(k_hmma<32,  3, false, true,  true,  false, false>, cudaFuncAttributeMaxDynamicSharedMemorySize, SM32);
    cudaFuncSetAttribute(k_hmma<64,  3, false, false, true,  false, false>, cudaFuncAttributeMaxDynamicSharedMemorySize, SM64);
    cudaFuncSetAttribute(k_step1, cudaFuncAttributeMaxDynamicSharedMemorySize, SMSTEP);

    auto mk = [](const __half* Ahi, const __half* Alo, const __half* Bhi,
                 const __half* Blo, const float* bias, const float* base,
                 float* C, __half* Chi, __half* Clo, int ldc) {
        Ops o; o.Ahi = Ahi; o.Alo = Alo; o.Bhi = Bhi; o.Blo = Blo;
        o.bias = bias; o.base = base; o.C = C; o.Chi = Chi; o.Clo = Clo;
        o.ldc = ldc; return o;
    };

    k_softmax_init<<<1, 256>>>(pscore, state0);

    // conversions (batched)
    k_half<<<(16384 * 768 / 4 + 255) / 256, 256>>>(video, vid_hi, 16384 * 768 / 4);
    {
        ST4 p;
        p.W[0] = mv_w1; p.hi[0] = mvw1t_hi; p.lo[0] = mvw1t_lo;
        p.W[1] = mv_w2; p.hi[1] = mvw2t_hi; p.lo[1] = mvw2t_lo;
        p.W[2] = mt_w1; p.hi[2] = mtw1t_hi; p.lo[2] = mtw1t_lo;
        p.W[3] = mt_w2; p.hi[3] = mtw2t_hi; p.lo[3] = mtw2t_lo;
        k_splitT4<<<dim3(24, 24, 4), 256>>>(p);
    }
    k_splitT<<<dim3(96, 48), 256>>>(mp_w1 + (size_t)1536 * 3072, mpw1rt_hi, mpw1rt_lo, 1536, 3072);
    k_splitT<<<dim3(24, 96), 256>>>(mp_w2, mpw2t_hi, mpw2t_lo, 3072, 768);
    {
        Split2 p;
        p.in[0] = wih; p.hi[0] = wih_hi; p.lo[0] = wih_lo; p.n4[0] = 2304 * 768 / 4;
        p.in[1] = whh; p.hi[1] = whh_hi; p.lo[1] = whh_lo; p.n4[1] = 2304 * 768 / 4;
        k_split2<<<dim3((2304 * 768 / 4 + 255) / 256, 1, 2), 256>>>(p);
    }
    {
        Split2 p;
        p.in[0] = a_texts;   p.hi[0] = atx_hi; p.lo[0] = atx_lo; p.n4[0] = 1024 * 768 / 4;
        p.in[1] = a_buttons; p.hi[1] = abt_hi; p.lo[1] = abt_lo; p.n4[1] = 1024 * 768 / 4;
        k_split2<<<dim3((1024 * 768 / 4 + 255) / 256, 1, 2), 256>>>(p);
    }

    // video L1 GEMM with fused segment mean (SEG)
    {
        Ops2 o2; o2.o[0] = o2.o[1] = mk(vid_hi, nullptr, mvw1t_hi, nullptr,
                                        mv_b1, nullptr, pseg, nullptr, nullptr, 768);
        k_hmma<128, 1, true, false, false, false, true><<<dim3(6, 128, 1), 256, SM128>>>(o2, 16384, 768, 768);
    }

    // para + question L1 (z-batched fp32)
    {
        G16x3 p;
        p.g[0] = {para,     mt_w1, mt_b1, pparah, 128};
        p.g[1] = {question, mt_w1, mt_b1, pqh,    8};
        p.g[2] = p.g[1];
        k_gemm16z<true><<<dim3(6, 8, 2), 256>>>(p, 768, 768);
    }
    // para L2, question L2, segmean@mv_w2 (z-batched fp32)
    {
        G16x3 p;
        p.g[0] = {pparah, mt_w2, mt_b2, pparao, 128};
        p.g[1] = {pqh,    mt_w2, mt_b2, pq,     8};
        p.g[2] = {pseg,   mv_w2, mv_b2, pvpo,   128};
        k_gemm16z<false><<<dim3(6, 8, 3), 256>>>(p, 768, 768);
    }
    // assemble vpq = [vp | pr | q]
    k_wsum3<<<dim3(3, 8, 3), 256>>>();

    // base = vpq @ mp_w1[0:2304] + mp_b1
    k_gemm16<false><<<dim3(24, 1), 256>>>(pvpq, mp_w1, mp_b1, pbase, 8, 3072, 2304);

    // fused L1 pair (MT=32)
    {
        Ops2 o2;
        o2.o[0] = mk(atx_hi, atx_lo, mtw1t_hi, mtw1t_lo, mt_b1, nullptr,
                     nullptr, tha_hi, tha_lo, 768);
        o2.o[1] = mk(abt_hi, abt_lo, mvw1t_hi, mvw1t_lo, mv_b1, nullptr,
                     nullptr, thb_hi, thb_lo, 768);
        k_hmma<32, 3, true, true, false, false, false><<<dim3(6, 32, 2), 256, SM32>>>(o2, 1024, 768, 768);
    }
    // fused L2 pair -> inpAB (MT=32)
    {
        Ops2 o2;
        o2.o[0] = mk(tha_hi, tha_lo, mtw2t_hi, mtw2t_lo, mt_b2, nullptr,
                     nullptr, inpAB_hi, inpAB_lo, 1536);
        o2.o[1] = mk(thb_hi, thb_lo, mvw2t_hi, mvw2t_lo, mv_b2, nullptr,
                     nullptr, inpAB_hi + 768, inpAB_lo + 768, 1536);
        k_hmma<32, 3, false, true, false, false, false><<<dim3(6, 32, 2), 256, SM32>>>(o2, 1024, 768, 768);
    }

    // row-part mlp_pre L1 (K=1536) + base add
    {
        Ops2 o2; o2.o[0] = o2.o[1] = mk(inpAB_hi, inpAB_lo, mpw1rt_hi, mpw1rt_lo,
                                        pzero, pbase, nullptr, preh_hi, preh_lo, 3072);
        k_hmma<64, 3, true, true, false, true, false><<<dim3(24, 16, 1), 256, SM64>>>(o2, 1024, 3072, 1536);
    }
    // mlp_pre L2 -> x (MT=32)
    {
        Ops2 o2; o2.o[0] = o2.o[1] = mk(preh_hi, preh_lo, mpw2t_hi, mpw2t_lo,
                                        mp_b2, nullptr, px, x_hi, x_lo, 768);
        k_hmma<32, 3, false, true, true, false, false><<<dim3(6, 32, 1), 256, SM32>>>(o2, 1024, 768, 3072);
    }
    // gi = x@wih^T+bih (z=0) AND gh_all = x@whh^T+bhh (z=1)
    {
        Ops2 o2;
        o2.o[0] = mk(x_hi, x_lo, wih_hi, wih_lo, bih, nullptr, pgi, nullptr, nullptr, 2304);
        o2.o[1] = mk(x_hi, x_lo, whh_hi, whh_lo, bhh, nullptr, pghall, nullptr, nullptr, 2304);
        k_hmma<64, 3, false, false, true, false, false><<<dim3(18, 16, 2), 256, SM64>>>(o2, 1024, 2304, 768);
    }

    // gh for step 0 (exact fp32, state0-based)
    k_gh<<<18, 128>>>(whh, bhh);

    // sequential scan: 2 launches/step
    for (int s = 0; s < 8; s++) {
        k_step1<<<dim3(6, 8), 256, SMSTEP>>>(s, pr_w1, pr_b1, pr_w2);
        k_step2<<<8, 32>>>(pr_b2, out, s);
    }
}

// round 11
// speedup vs baseline: 1.0555x; 1.0555x over previous
#include <cuda_runtime.h>
#include <cuda_fp16.h>
#include <math.h>
#include <stdint.h>

// B=8, T=2048, P=16, S=8, A=16, D=768, H=768, 3H=2304, 4D=3072

// ==================== scratch (device globals) ====================
__device__ float g_ps[8 * 16];
__device__ __align__(16) float g_h[8 * 768];
__device__ float g_segmean[128 * 768];
__device__ float g_vpo[128 * 768];
__device__ float g_para_h[128 * 768];
__device__ float g_para_o[128 * 768];
__device__ float g_qh[8 * 768];
__device__ float g_q[8 * 768];
__device__ float g_vpq[8 * 2304];
__device__ float g_zero[3072];
__device__ float g_base[8 * 3072];
__device__ __align__(128) float g_x[1024 * 768];
__device__ __align__(128) float g_gi[1024 * 2304];
__device__ __align__(128) float g_ghall[1024 * 2304];
__device__ __align__(16) float g_gh[8 * 2304];
__device__ float g_logpart[6 * 128];
__device__ int g_best[8];

// fp16 buffers (hi/lo split)
__device__ __align__(128) __half g_vid_hi[16384 * 768];
__device__ __align__(128) __half g_atx_hi[1024 * 768];
__device__ __align__(128) __half g_atx_lo[1024 * 768];
__device__ __align__(128) __half g_abt_hi[1024 * 768];
__device__ __align__(128) __half g_abt_lo[1024 * 768];
__device__ __align__(128) __half g_wih_hi[2304 * 768];
__device__ __align__(128) __half g_wih_lo[2304 * 768];
__device__ __align__(128) __half g_whh_hi[2304 * 768];
__device__ __align__(128) __half g_whh_lo[2304 * 768];
__device__ __align__(128) __half g_mvw1t_hi[768 * 768];
__device__ __align__(128) __half g_mvw1t_lo[768 * 768];
__device__ __align__(128) __half g_mvw2t_hi[768 * 768];
__device__ __align__(128) __half g_mvw2t_lo[768 * 768];
__device__ __align__(128) __half g_mtw1t_hi[768 * 768];
__device__ __align__(128) __half g_mtw1t_lo[768 * 768];
__device__ __align__(128) __half g_mtw2t_hi[768 * 768];
__device__ __align__(128) __half g_mtw2t_lo[768 * 768];
__device__ __align__(128) __half g_mpw1rt_hi[3072 * 1536];
__device__ __align__(128) __half g_mpw1rt_lo[3072 * 1536];
__device__ __align__(128) __half g_mpw2t_hi[768 * 3072];
__device__ __align__(128) __half g_mpw2t_lo[768 * 3072];
__device__ __align__(128) __half g_tha_hi[1024 * 768];
__device__ __align__(128) __half g_tha_lo[1024 * 768];
__device__ __align__(128) __half g_thb_hi[1024 * 768];
__device__ __align__(128) __half g_thb_lo[1024 * 768];
__device__ __align__(128) __half g_inpAB_hi[1024 * 1536];
__device__ __align__(128) __half g_inpAB_lo[1024 * 1536];
__device__ __align__(128) __half g_preh_hi[1024 * 3072];
__device__ __align__(128) __half g_preh_lo[1024 * 3072];
__device__ __align__(128) __half g_x_hi[1024 * 768];
__device__ __align__(128) __half g_x_lo[1024 * 768];

// ==================== mma.sync helpers ====================
__device__ __forceinline__ void ldm_x4(uint32_t f[4], uint32_t addr) {
    asm volatile("ldmatrix.sync.aligned.m8n8.x4.shared.b16 {%0,%1,%2,%3}, [%4];"
                 : "=r"(f[0]), "=r"(f[1]), "=r"(f[2]), "=r"(f[3]) : "r"(addr));
}
__device__ __forceinline__ void mma16816(float* c, const uint32_t a[4],
                                         uint32_t b0, uint32_t b1) {
    asm volatile(
        "mma.sync.aligned.m16n8k16.row.col.f32.f16.f16.f32 "
        "{%0,%1,%2,%3}, {%4,%5,%6,%7}, {%8,%9}, {%0,%1,%2,%3};"
        : "+f"(c[0]), "+f"(c[1]), "+f"(c[2]), "+f"(c[3])
        : "r"(a[0]), "r"(a[1]), "r"(a[2]), "r"(a[3]), "r"(b0), "r"(b1));
}
#define CP_ASYNC16(dst, src) \
    asm volatile("cp.async.cg.shared.global [%0], [%1], 16;" :: "r"(dst), "l"(src))
#define CP_COMMIT() asm volatile("cp.async.commit_group;")
#define CP_WAIT(n)  asm volatile("cp.async.wait_group %0;" :: "n"(n))

struct Ops {
    const __half *Ahi, *Alo, *Bhi, *Blo;
    const float* bias;
    const float* base;
    float* C;
    __half *Chi, *Clo;
    int ldc;
};
struct Ops2 { Ops o[2]; };

// ==================== HMMA GEMM (proven core) ====================
template <int MT, int NPROD, bool RELU, bool SPLITOUT, bool F32OUT, bool BADD, bool SEG>
__global__ void __launch_bounds__(256, 2) k_hmma(Ops2 ops, int M, int N, int K)
{
    const Ops op = ops.o[blockIdx.z];
    extern __shared__ __align__(128) char smem[];
    const uint32_t s_base = (uint32_t)__cvta_generic_to_shared(smem);
    constexpr int STAGE_BYTES = (MT + 128) * 128;
    constexpr int MI = MT / 32;
    constexpr int KADV = (NPROD == 3) ? 32 : 64;
    constexpr int ACP = MT * 8;

    const int tid = threadIdx.x;
    const int wid = tid >> 5, lane = tid & 31;
    const int wm = wid & 1, wn = wid >> 1;
    const int row0 = blockIdx.y * MT;
    const int col0 = blockIdx.x * 128;
    const int NC = K / KADV;

    float acc[MI][4][4];
    #pragma unroll
    for (int i = 0; i < MI; i++)
        #pragma unroll
        for (int j = 0; j < 4; j++)
            #pragma unroll
            for (int r = 0; r < 4; r++) acc[i][j][r] = 0.f;

    auto load_stage = [&](int c) {
        const int k0 = c * KADV;
        const uint32_t sb = s_base + (uint32_t)((c & 1) * STAGE_BYTES);
        #pragma unroll
        for (int i = tid; i < ACP + 1024; i += 256) {
            const bool isA = i < ACP;
            const int e = isA ? i : i - ACP;
            const int row = e >> 3, ch = e & 7;
            const int grow = (isA ? row0 : col0) + row;
            const __half* src;
            if (NPROD == 3) {
                const int o2 = ch >> 2, kc = ch & 3;
                const __half* base = isA ? (o2 ? op.Alo : op.Ahi) : (o2 ? op.Blo : op.Bhi);
                src = base + (size_t)grow * K + k0 + kc * 8;
            } else {
                src = (isA ? op.Ahi : op.Bhi) + (size_t)grow * K + k0 + ch * 8;
            }
            const uint32_t dst = sb + (uint32_t)((isA ? 0 : MT * 128)
                               + row * 128 + ((ch ^ (row & 7)) << 4));
            CP_ASYNC16(dst, src);
        }
        CP_COMMIT();
    };

    load_stage(0);

    for (int c = 0; c < NC; c++) {
        if (c + 1 < NC) { load_stage(c + 1); CP_WAIT(1); }
        else            { CP_WAIT(0); }
        __syncthreads();

        const uint32_t sA = s_base + (uint32_t)((c & 1) * STAGE_BYTES);
        const uint32_t sB = sA + MT * 128;
        constexpr int NK = (NPROD == 3) ? 2 : 4;

        #pragma unroll
        for (int s = 0; s < NK; s++) {
            uint32_t ah[MI][4], bh[2][4];
            #pragma unroll
            for (int mt = 0; mt < MI; mt++) {
                const int row = wm * (MT / 2) + mt * 16 + (lane & 15);
                const int ch = s * 2 + (lane >> 4);
                ldm_x4(ah[mt], sA + row * 128 + ((ch ^ (row & 7)) << 4));
            }
            #pragma unroll
            for (int ntp = 0; ntp < 2; ntp++) {
                const int row = wn * 32 + ntp * 16 + ((lane >> 4) << 3) + (lane & 7);
                const int ch = s * 2 + ((lane >> 3) & 1);
                ldm_x4(bh[ntp], sB + row * 128 + ((ch ^ (row & 7)) << 4));
            }
            if (NPROD == 3) {
                uint32_t al[MI][4], bl[2][4];
                #pragma unroll
                for (int mt = 0; mt < MI; mt++) {
                    const int row = wm * (MT / 2) + mt * 16 + (lane & 15);
                    const int ch = 4 + s * 2 + (lane >> 4);
                    ldm_x4(al[mt], sA + row * 128 + ((ch ^ (row & 7)) << 4));
                }
                #pragma unroll
                for (int ntp = 0; ntp < 2; ntp++) {
                    const int row = wn * 32 + ntp * 16 + ((lane >> 4) << 3) + (lane & 7);
                    const int ch = 4 + s * 2 + ((lane >> 3) & 1);
                    ldm_x4(bl[ntp], sB + row * 128 + ((ch ^ (row & 7)) << 4));
                }
                #pragma unroll
                for (int mt = 0; mt < MI; mt++)
                    #pragma unroll
                    for (int nt = 0; nt < 4; nt++) {
                        const int p = nt >> 1, q = (nt & 1) * 2;
                        mma16816(acc[mt][nt], ah[mt], bh[p][q], bh[p][q + 1]);
                        mma16816(acc[mt][nt], ah[mt], bl[p][q], bl[p][q + 1]);
                        mma16816(acc[mt][nt], al[mt], bh[p][q], bh[p][q + 1]);
                    }
            } else {
                #pragma unroll
                for (int mt = 0; mt < MI; mt++)
                    #pragma unroll
                    for (int nt = 0; nt < 4; nt++) {
                        const int p = nt >> 1, q = (nt & 1) * 2;
                        mma16816(acc[mt][nt], ah[mt], bh[p][q], bh[p][q + 1]);
                    }
            }
        }
        __syncthreads();
    }

    float csum[4][2];
    if (SEG) {
        #pragma unroll
        for (int nt = 0; nt < 4; nt++) { csum[nt][0] = 0.f; csum[nt][1] = 0.f; }
    }
    #pragma unroll
    for (int mt = 0; mt < MI; mt++) {
        #pragma unroll
        for (int nt = 0; nt < 4; nt++) {
            const int col = col0 + wn * 32 + nt * 8 + (lane & 3) * 2;
            const float2 bv = *reinterpret_cast<const float2*>(op.bias + col);
            #pragma unroll
            for (int half = 0; half < 2; half++) {
                const int grow = row0 + wm * (MT / 2) + mt * 16 + (lane >> 2) + half * 8;
                float v0 = acc[mt][nt][half * 2 + 0] + bv.x;
                float v1 = acc[mt][nt][half * 2 + 1] + bv.y;
                if (BADD) {
                    const float2 bsv = *reinterpret_cast<const float2*>(
                        op.base + (size_t)(grow >> 7) * 3072 + col);
                    v0 += bsv.x; v1 += bsv.y;
                }
                if (RELU) { v0 = fmaxf(v0, 0.f); v1 = fmaxf(v1, 0.f); }
                if (SEG) { csum[nt][0] += v0; csum[nt][1] += v1; }
                if (F32OUT)
                    *reinterpret_cast<float2*>(op.C + (size_t)grow * op.ldc + col) =
                        make_float2(v0, v1);
                if (SPLITOUT) {
                    const __half h0 = __float2half_rn(v0);
                    const __half h1 = __float2half_rn(v1);
                    const __half l0 = __float2half_rn(v0 - __half2float(h0));
                    const __half l1 = __float2half_rn(v1 - __half2float(h1));
                    *reinterpret_cast<__half2*>(op.Chi + (size_t)grow * op.ldc + col) =
                        make_half2(h0, h1);
                    *reinterpret_cast<__half2*>(op.Clo + (size_t)grow * op.ldc + col) =
                        make_half2(l0, l1);
                }
            }
        }
    }
    if (SEG) {
        #pragma unroll
        for (int o = 4; o <= 16; o <<= 1)
            #pragma unroll
            for (int nt = 0; nt < 4; nt++) {
                csum[nt][0] += __shfl_xor_sync(0xffffffffu, csum[nt][0], o);
                csum[nt][1] += __shfl_xor_sync(0xffffffffu, csum[nt][1], o);
            }
        float* scol = reinterpret_cast<float*>(smem);
        if (tid < 128) scol[tid] = 0.f;
        __syncthreads();
        if ((lane >> 2) == 0) {
            #pragma unroll
            for (int nt = 0; nt < 4; nt++) {
                atomicAdd(&scol[wn * 32 + nt * 8 + (lane & 3) * 2 + 0], csum[nt][0]);
                atomicAdd(&scol[wn * 32 + nt * 8 + (lane & 3) * 2 + 1], csum[nt][1]);
            }
        }
        __syncthreads();
        if (tid < 128)
            op.C[(size_t)blockIdx.y * 768 + col0 + tid] = scol[tid] * (1.f / 128.f);
    }
}

// ==================== conversion kernels (batched) ====================
__global__ void k_half(const float* __restrict__ in, __half* __restrict__ hi, int n4) {
    int i = blockIdx.x * 256 + threadIdx.x;
    if (i >= n4) return;
    float4 v = reinterpret_cast<const float4*>(in)[i];
    reinterpret_cast<__half2*>(hi)[i * 2 + 0] =
        make_half2(__float2half_rn(v.x), __float2half_rn(v.y));
    reinterpret_cast<__half2*>(hi)[i * 2 + 1] =
        make_half2(__float2half_rn(v.z), __float2half_rn(v.w));
}

struct Split2 { const float* in[2]; __half* hi[2]; __half* lo[2]; int n4[2]; };
__global__ void k_split2(Split2 p) {
    const int z = blockIdx.z;
    int i = blockIdx.x * 256 + threadIdx.x;
    if (i >= p.n4[z]) return;
    float4 v = reinterpret_cast<const float4*>(p.in[z])[i];
    __half h0 = __float2half_rn(v.x), h1 = __float2half_rn(v.y);
    __half h2 = __float2half_rn(v.z), h3 = __float2half_rn(v.w);
    __half l0 = __float2half_rn(v.x - __half2float(h0));
    __half l1 = __float2half_rn(v.y - __half2float(h1));
    __half l2 = __float2half_rn(v.z - __half2float(h2));
    __half l3 = __float2half_rn(v.w - __half2float(h3));
    reinterpret_cast<__half2*>(p.hi[z])[i * 2 + 0] = make_half2(h0, h1);
    reinterpret_cast<__half2*>(p.hi[z])[i * 2 + 1] = make_half2(h2, h3);
    reinterpret_cast<__half2*>(p.lo[z])[i * 2 + 0] = make_half2(l0, l1);
    reinterpret_cast<__half2*>(p.lo[z])[i * 2 + 1] = make_half2(l2, l3);
}

__global__ void k_splitT(const float* __restrict__ W, __half* __restrict__ hi,
                         __half* __restrict__ lo, int K, int N) {
    __shared__ float t[32][33];
    const int kb = blockIdx.y * 32, nb = blockIdx.x * 32;
    const int tx = threadIdx.x & 31, ty = threadIdx.x >> 5;
    #pragma unroll
    for (int r = ty; r < 32; r += 8)
        t[r][tx] = W[(size_t)(kb + r) * N + nb + tx];
    __syncthreads();
    #pragma unroll
    for (int r = ty; r < 32; r += 8) {
        float v = t[tx][r];
        __half h = __float2half_rn(v);
        __half l = __float2half_rn(v - __half2float(h));
        size_t o = (size_t)(nb + r) * K + kb + tx;
        hi[o] = h;
        lo[o] = l;
    }
}

struct ST4 { const float* W[4]; __half* hi[4]; __half* lo[4]; };
__global__ void k_splitT4(ST4 p) {   // all 768x768
    const int z = blockIdx.z;
    __shared__ float t[32][33];
    const int kb = blockIdx.y * 32, nb = blockIdx.x * 32;
    const int tx = threadIdx.x & 31, ty = threadIdx.x >> 5;
    #pragma unroll
    for (int r = ty; r < 32; r += 8)
        t[r][tx] = p.W[z][(size_t)(kb + r) * 768 + nb + tx];
    __syncthreads();
    #pragma unroll
    for (int r = ty; r < 32; r += 8) {
        float v = t[tx][r];
        __half h = __float2half_rn(v);
        __half l = __float2half_rn(v - __half2float(h));
        size_t o = (size_t)(nb + r) * 768 + kb + tx;
        p.hi[z][o] = h;
        p.lo[z][o] = l;
    }
}

// ==================== fp32 helper kernels ====================
__global__ void k_softmax_init(const float* __restrict__ scores,
                               const float* __restrict__ state0) {
    int tid = threadIdx.x;
    int warp = tid >> 5, lane = tid & 31;
    if (warp < 8) {
        float v = (lane < 16) ? scores[warp * 16 + lane] : -1e30f;
        float m = v;
        #pragma unroll
        for (int o = 16; o > 0; o >>= 1) m = fmaxf(m, __shfl_xor_sync(0xffffffffu, m, o));
        float e = (lane < 16) ? expf(v - m) : 0.f;
        float s = e;
        #pragma unroll
        for (int o = 16; o > 0; o >>= 1) s += __shfl_xor_sync(0xffffffffu, s, o);
        if (lane < 16) g_ps[warp * 16 + lane] = e / s;
    }
    for (int i = tid; i < 8 * 768; i += blockDim.x) g_h[i] = state0[i % 768];
    for (int i = tid; i < 3072; i += blockDim.x) g_zero[i] = 0.f;
}

template <bool RELU>
__global__ void __launch_bounds__(256) k_gemm16(
    const float* __restrict__ A, const float* __restrict__ W,
    const float* __restrict__ bias, float* __restrict__ C,
    int M, int N, int K) {
    __shared__ __align__(16) float As[32][16];
    __shared__ __align__(16) float Ws[32][128];
    const int tid = threadIdx.x;
    const int row0 = blockIdx.y * 16;
    const int col0 = blockIdx.x * 128;
    const int row = tid >> 4;
    const int cg = tid & 15;
    float acc[8];
    #pragma unroll
    for (int j = 0; j < 8; j++) acc[j] = 0.f;
    for (int k0 = 0; k0 < K; k0 += 32) {
        if (tid < 128) {
            int ar = tid >> 3, ac = (tid & 7) * 4;
            float4 av = make_float4(0.f, 0.f, 0.f, 0.f);
            int gr = row0 + ar;
            if (gr < M) av = *reinterpret_cast<const float4*>(A + (size_t)gr * K + k0 + ac);
            As[ac + 0][ar] = av.x; As[ac + 1][ar] = av.y;
            As[ac + 2][ar] = av.z; As[ac + 3][ar] = av.w;
        }
        #pragma unroll
        for (int j = 0; j < 4; j++) {
            int wr = (tid >> 5) + j * 8;
            int wc = (tid & 31) * 4;
            float4 wv = *reinterpret_cast<const float4*>(W + (size_t)(k0 + wr) * N + col0 + wc);
            *reinterpret_cast<float4*>(&Ws[wr][wc]) = wv;
        }
        __syncthreads();
        #pragma unroll
        for (int k = 0; k < 32; k++) {
            float a = As[k][row];
            float4 b0 = *reinterpret_cast<const float4*>(&Ws[k][cg * 4]);
            float4 b1 = *reinterpret_cast<const float4*>(&Ws[k][64 + cg * 4]);
            acc[0] = fmaf(a, b0.x, acc[0]); acc[1] = fmaf(a, b0.y, acc[1]);
            acc[2] = fmaf(a, b0.z, acc[2]); acc[3] = fmaf(a, b0.w, acc[3]);
            acc[4] = fmaf(a, b1.x, acc[4]); acc[5] = fmaf(a, b1.y, acc[5]);
            acc[6] = fmaf(a, b1.z, acc[6]); acc[7] = fmaf(a, b1.w, acc[7]);
        }
        __syncthreads();
    }
    int r = row0 + row;
    if (r < M) {
        float4 bv0 = *reinterpret_cast<const float4*>(bias + col0 + cg * 4);
        float4 bv1 = *reinterpret_cast<const float4*>(bias + col0 + 64 + cg * 4);
        float o[8];
        o[0] = acc[0] + bv0.x; o[1] = acc[1] + bv0.y;
        o[2] = acc[2] + bv0.z; o[3] = acc[3] + bv0.w;
        o[4] = acc[4] + bv1.x; o[5] = acc[5] + bv1.y;
        o[6] = acc[6] + bv1.z; o[7] = acc[7] + bv1.w;
        if (RELU) {
            #pragma unroll
            for (int j = 0; j < 8; j++) o[j] = fmaxf(o[j], 0.f);
        }
        *reinterpret_cast<float4*>(C + (size_t)r * N + col0 + cg * 4) =
            make_float4(o[0], o[1], o[2], o[3]);
        *reinterpret_cast<float4*>(C + (size_t)r * N + col0 + 64 + cg * 4) =
            make_float4(o[4], o[5], o[6], o[7]);
    }
}

struct G16 { const float* A; const float* W; const float* bias; float* C; int M; };
struct G16x3 { G16 g[3]; };
template <bool RELU>
__global__ void __launch_bounds__(256) k_gemm16z(G16x3 p, int N, int K) {
    const G16 gz = p.g[blockIdx.z];
    const int row0 = blockIdx.y * 16;
    if (row0 >= gz.M) return;
    __shared__ __align__(16) float As[32][16];
    __shared__ __align__(16) float Ws[32][128];
    const int tid = threadIdx.x;
    const int col0 = blockIdx.x * 128;
    const int row = tid >> 4;
    const int cg = tid & 15;
    float acc[8];
    #pragma unroll
    for (int j = 0; j < 8; j++) acc[j] = 0.f;
    for (int k0 = 0; k0 < K; k0 += 32) {
        if (tid < 128) {
            int ar = tid >> 3, ac = (tid & 7) * 4;
            float4 av = make_float4(0.f, 0.f, 0.f, 0.f);
            int gr = row0 + ar;
            if (gr < gz.M) av = *reinterpret_cast<const float4*>(gz.A + (size_t)gr * K + k0 + ac);
            As[ac + 0][ar] = av.x; As[ac + 1][ar] = av.y;
            As[ac + 2][ar] = av.z; As[ac + 3][ar] = av.w;
        }
        #pragma unroll
        for (int j = 0; j < 4; j++) {
            int wr = (tid >> 5) + j * 8;
            int wc = (tid & 31) * 4;
            float4 wv = *reinterpret_cast<const float4*>(gz.W + (size_t)(k0 + wr) * N + col0 + wc);
            *reinterpret_cast<float4*>(&Ws[wr][wc]) = wv;
        }
        __syncthreads();
        #pragma unroll
        for (int k = 0; k < 32; k++) {
            float a = As[k][row];
            float4 b0 = *reinterpret_cast<const float4*>(&Ws[k][cg * 4]);
            float4 b1 = *reinterpret_cast<const float4*>(&Ws[k][64 + cg * 4]);
            acc[0] = fmaf(a, b0.x, acc[0]); acc[1] = fmaf(a, b0.y, acc[1]);
            acc[2] = fmaf(a, b0.z, acc[2]); acc[3] = fmaf(a, b0.w, acc[3]);
            acc[4] = fmaf(a, b1.x, acc[4]); acc[5] = fmaf(a, b1.y, acc[5]);
            acc[6] = fmaf(a, b1.z, acc[6]); acc[7] = fmaf(a, b1.w, acc[7]);
        }
        __syncthreads();
    }
    int r = row0 + row;
    if (r < gz.M) {
        float4 bv0 = *reinterpret_cast<const float4*>(gz.bias + col0 + cg * 4);
        float4 bv1 = *reinterpret_cast<const float4*>(gz.bias + col0 + 64 + cg * 4);
        float o[8];
        o[0] = acc[0] + bv0.x; o[1] = acc[1] + bv0.y;
        o[2] = acc[2] + bv0.z; o[3] = acc[3] + bv0.w;
        o[4] = acc[4] + bv1.x; o[5] = acc[5] + bv1.y;
        o[6] = acc[6] + bv1.z; o[7] = acc[7] + bv1.w;
        if (RELU) {
            #pragma unroll
            for (int j = 0; j < 8; j++) o[j] = fmaxf(o[j], 0.f);
        }
        *reinterpret_cast<float4*>(gz.C + (size_t)r * N + col0 + cg * 4) =
            make_float4(o[0], o[1], o[2], o[3]);
        *reinterpret_cast<float4*>(gz.C + (size_t)r * N + col0 + 64 + cg * 4) =
            make_float4(o[4], o[5], o[6], o[7]);
    }
}

__global__ void k_wsum3() {
    const int z = blockIdx.z;
    const int b = blockIdx.y;
    const int d = blockIdx.x * 256 + threadIdx.x;
    if (z == 2) {
        g_vpq[b * 2304 + 1536 + d] = g_q[b * 768 + d];
        return;
    }
    const float* in = (z == 0) ? g_vpo : g_para_o;
    float acc = 0.f;
    #pragma unroll
    for (int p = 0; p < 16; p++)
        acc = fmaf(g_ps[b * 16 + p], in[(size_t)(b * 16 + p) * 768 + d], acc);
    g_vpq[b * 2304 + z * 768 + d] = acc;
}

__global__ void __launch_bounds__(128) k_gh(const float* __restrict__ whh,
                                            const float* __restrict__ bhh) {
    __shared__ float hs[8 * 768];
    for (int i = threadIdx.x; i < 8 * 768; i += 128) hs[i] = g_h[i];
    __syncthreads();
    int n = blockIdx.x * 128 + threadIdx.x;
    float bv = bhh[n];
    float acc[8];
    #pragma unroll
    for (int b = 0; b < 8; b++) acc[b] = bv;
    const float4* wr = reinterpret_cast<const float4*>(whh + (size_t)n * 768);
    #pragma unroll 4
    for (int k4 = 0; k4 < 192; k4++) {
        float4 w = wr[k4];
        int kb = k4 * 4;
        #pragma unroll
        for (int b = 0; b < 8; b++) {
            const float* hb = hs + b * 768 + kb;
            acc[b] = fmaf(w.x, hb[0], fmaf(w.y, hb[1], fmaf(w.z, hb[2], fmaf(w.w, hb[3], acc[b]))));
        }
    }
    #pragma unroll
    for (int b = 0; b < 8; b++) g_gh[b * 2304 + n] = acc[b];
}

// ==================== fused scan step 1 ====================
__global__ void __launch_bounds__(256) k_step1(
    int s, const float* __restrict__ w1, const float* __restrict__ b1,
    const float* __restrict__ w2)
{
    extern __shared__ float dsm[];
    float* st = dsm;
    float* Ws = dsm + 16 * 768;
    const int tid = threadIdx.x;
    const int row0 = blockIdx.y * 16;
    const int col0 = blockIdx.x * 128;

    for (int idx = tid; idx < 16 * 768; idx += 256) {
        const int rr = idx / 768, hh = idx - rr * 768;
        const int r = row0 + rr;
        const int b = r >> 4, a = r & 15;
        const size_t gib = (size_t)((b * 8 + s) * 16 + a) * 2304;
        const float* ghrow;
        const float* hprev;
        if (s == 0) {
            ghrow = g_gh + b * 2304;
            hprev = g_h + b * 768;
        } else {
            const int prev = (b * 8 + (s - 1)) * 16 + g_best[b];
            ghrow = g_ghall + (size_t)prev * 2304;
            hprev = g_x + (size_t)prev * 768;
        }
        const float ir = g_gi[gib + hh];
        const float iz = g_gi[gib + 768 + hh];
        const float in_ = g_gi[gib + 1536 + hh];
        const float rr_ = 1.f / (1.f + expf(-(ir + ghrow[hh])));
        const float zz = 1.f / (1.f + expf(-(iz + ghrow[768 + hh])));
        const float nn = tanhf(in_ + rr_ * ghrow[1536 + hh]);
        st[rr * 768 + hh] = (1.f - zz) * nn + zz * hprev[hh];
    }
    __syncthreads();

    const int row = tid >> 4, cg = tid & 15;
    float acc[8];
    #pragma unroll
    for (int j = 0; j < 8; j++) acc[j] = 0.f;
    for (int k0 = 0; k0 < 768; k0 += 32) {
        #pragma unroll
        for (int j = 0; j < 4; j++) {
            const int wr = (tid >> 5) + j * 8;
            const int wc = (tid & 31) * 4;
            *reinterpret_cast<float4*>(&Ws[wr * 128 + wc]) =
                *reinterpret_cast<const float4*>(w1 + (size_t)(k0 + wr) * 768 + col0 + wc);
        }
        __syncthreads();
        #pragma unroll
        for (int k = 0; k < 32; k++) {
            const float a = st[row * 768 + k0 + k];
            const float4 b0 = *reinterpret_cast<const float4*>(&Ws[k * 128 + cg * 4]);
            const float4 b1v = *reinterpret_cast<const float4*>(&Ws[k * 128 + 64 + cg * 4]);
            acc[0] = fmaf(a, b0.x, acc[0]); acc[1] = fmaf(a, b0.y, acc[1]);
            acc[2] = fmaf(a, b0.z, acc[2]); acc[3] = fmaf(a, b0.w, acc[3]);
            acc[4] = fmaf(a, b1v.x, acc[4]); acc[5] = fmaf(a, b1v.y, acc[5]);
            acc[6] = fmaf(a, b1v.z, acc[6]); acc[7] = fmaf(a, b1v.w, acc[7]);
        }
        __syncthreads();
    }

    const float4 bv0 = *reinterpret_cast<const float4*>(b1 + col0 + cg * 4);
    const float4 bv1 = *reinterpret_cast<const float4*>(b1 + col0 + 64 + cg * 4);
    const float4 w20 = *reinterpret_cast<const float4*>(w2 + col0 + cg * 4);
    const float4 w21 = *reinterpret_cast<const float4*>(w2 + col0 + 64 + cg * 4);
    float part = 0.f;
    part += fmaxf(acc[0] + bv0.x, 0.f) * w20.x;
    part += fmaxf(acc[1] + bv0.y, 0.f) * w20.y;
    part += fmaxf(acc[2] + bv0.z, 0.f) * w20.z;
    part += fmaxf(acc[3] + bv0.w, 0.f) * w20.w;
    part += fmaxf(acc[4] + bv1.x, 0.f) * w21.x;
    part += fmaxf(acc[5] + bv1.y, 0.f) * w21.y;
    part += fmaxf(acc[6] + bv1.z, 0.f) * w21.z;
    part += fmaxf(acc[7] + bv1.w, 0.f) * w21.w;
    #pragma unroll
    for (int off = 1; off < 16; off <<= 1)
        part += __shfl_xor_sync(0xffffffffu, part, off);
    if (cg == 0)
        g_logpart[blockIdx.x * 128 + row0 + row] = part;
}

__global__ void k_step2(const float* __restrict__ b2, float* __restrict__ out, int s) {
    const int b = blockIdx.x;
    const int lane = threadIdx.x;
    float val = -1e30f;
    int idx = 1000;
    if (lane < 16) {
        float lg = b2[0];
        #pragma unroll
        for (int x = 0; x < 6; x++) lg += g_logpart[x * 128 + b * 16 + lane];
        out[(b * 8 + s) * 16 + lane] = lg;
        val = lg;
        idx = lane;
    }
    #pragma unroll
    for (int off = 8; off > 0; off >>= 1) {
        const float oval = __shfl_down_sync(0xffffffffu, val, off);
        const int oidx = __shfl_down_sync(0xffffffffu, idx, off);
        if (oval > val || (oval == val && oidx < idx)) { val = oval; idx = oidx; }
    }
    if (lane == 0) g_best[b] = idx;
}

// ==================== host ====================
#define GETSYM(p, s) cudaGetSymbolAddress((void**)&(p), s)

extern "C" void kernel_launch(void* const* d_in, const int* in_sizes, int n_in,
                              void* d_out, int out_size) {
    (void)in_sizes; (void)n_in; (void)out_size;
    const float* video     = (const float*)d_in[0];
    const float* para      = (const float*)d_in[1];
    const float* question  = (const float*)d_in[2];
    const float* pscore    = (const float*)d_in[3];
    const float* a_texts   = (const float*)d_in[4];
    const float* a_buttons = (const float*)d_in[5];
    const float* mv_w1 = (const float*)d_in[6],  *mv_b1 = (const float*)d_in[7];
    const float* mv_w2 = (const float*)d_in[8],  *mv_b2 = (const float*)d_in[9];
    const float* mt_w1 = (const float*)d_in[10], *mt_b1 = (const float*)d_in[11];
    const float* mt_w2 = (const float*)d_in[12], *mt_b2 = (const float*)d_in[13];
    const float* mp_w1 = (const float*)d_in[14], *mp_b1 = (const float*)d_in[15];
    const float* mp_w2 = (const float*)d_in[16], *mp_b2 = (const float*)d_in[17];
    const float* wih   = (const float*)d_in[18], *bih   = (const float*)d_in[19];
    const float* whh   = (const float*)d_in[20], *bhh   = (const float*)d_in[21];
    const float* pr_w1 = (const float*)d_in[22], *pr_b1 = (const float*)d_in[23];
    const float* pr_w2 = (const float*)d_in[24], *pr_b2 = (const float*)d_in[25];
    const float* state0 = (const float*)d_in[26];
    float* out = (float*)d_out;

    float *pseg, *pvpo, *pparah, *pparao, *pqh, *pq;
    float *pvpq, *pzero, *pbase, *px, *pgi, *pghall;
    GETSYM(pseg, g_segmean); GETSYM(pvpo, g_vpo);
    GETSYM(pparah, g_para_h); GETSYM(pparao, g_para_o);
    GETSYM(pqh, g_qh); GETSYM(pq, g_q);
    GETSYM(pvpq, g_vpq); GETSYM(pzero, g_zero); GETSYM(pbase, g_base);
    GETSYM(px, g_x); GETSYM(pgi, g_gi); GETSYM(pghall, g_ghall);

    __half *vid_hi, *atx_hi, *atx_lo, *abt_hi, *abt_lo;
    __half *wih_hi, *wih_lo, *whh_hi, *whh_lo;
    __half *mvw1t_hi, *mvw1t_lo, *mvw2t_hi, *mvw2t_lo, *mtw1t_hi, *mtw1t_lo;
    __half *mtw2t_hi, *mtw2t_lo, *mpw1rt_hi, *mpw1rt_lo, *mpw2t_hi, *mpw2t_lo;
    __half *tha_hi, *tha_lo, *thb_hi, *thb_lo, *inpAB_hi, *inpAB_lo;
    __half *preh_hi, *preh_lo, *x_hi, *x_lo;
    GETSYM(vid_hi, g_vid_hi);
    GETSYM(atx_hi, g_atx_hi); GETSYM(atx_lo, g_atx_lo);
    GETSYM(abt_hi, g_abt_hi); GETSYM(abt_lo, g_abt_lo);
    GETSYM(wih_hi, g_wih_hi); GETSYM(wih_lo, g_wih_lo);
    GETSYM(whh_hi, g_whh_hi); GETSYM(whh_lo, g_whh_lo);
    GETSYM(mvw1t_hi, g_mvw1t_hi); GETSYM(mvw1t_lo, g_mvw1t_lo);
    GETSYM(mvw2t_hi, g_mvw2t_hi); GETSYM(mvw2t_lo, g_mvw2t_lo);
    GETSYM(mtw1t_hi, g_mtw1t_hi); GETSYM(mtw1t_lo, g_mtw1t_lo);
    GETSYM(mtw2t_hi, g_mtw2t_hi); GETSYM(mtw2t_lo, g_mtw2t_lo);
    GETSYM(mpw1rt_hi, g_mpw1rt_hi); GETSYM(mpw1rt_lo, g_mpw1rt_lo);
    GETSYM(mpw2t_hi, g_mpw2t_hi); GETSYM(mpw2t_lo, g_mpw2t_lo);
    GETSYM(tha_hi, g_tha_hi); GETSYM(tha_lo, g_tha_lo);
    GETSYM(thb_hi, g_thb_hi); GETSYM(thb_lo, g_thb_lo);
    GETSYM(inpAB_hi, g_inpAB_hi); GETSYM(inpAB_lo, g_inpAB_lo);
    GETSYM(preh_hi, g_preh_hi); GETSYM(preh_lo, g_preh_lo);
    GETSYM(x_hi, g_x_hi); GETSYM(x_lo, g_x_lo);

    constexpr int SM128 = (128 + 128) * 128 * 2;
    constexpr int SM64  = (64 + 128) * 128 * 2;
    constexpr int SM32  = (32 + 128) * 128 * 2;
    constexpr int SMSTEP = 16 * 768 * 4 + 32 * 128 * 4;
    cudaFuncSetAttribute(k_hmma<128, 1, true,  false, false, false, true >, cudaFuncAttributeMaxDynamicSharedMemorySize, SM128);
    cudaFuncSetAttribute(k_hmma<32,  3, true,  true,  false, false, false>, cudaFuncAttributeMaxDynamicSharedMemorySize, SM32);
    cudaFuncSetAttribute(k_hmma<32,  3, false, true,  false, false, false>, cudaFuncAttributeMaxDynamicSharedMemorySize, SM32);
    cudaFuncSetAttribute(k_hmma<64,  3, true,  true,  false, true,  false>, cudaFuncAttributeMaxDynamicSharedMemorySize, SM64);
    cudaFuncSetAttribute(k_hmma<32,  3, false, true,  true,  false, false>, cudaFuncAttributeMaxDynamicSharedMemorySize, SM32);
    cudaFuncSetAttribute(k_hmma<64,  3, false, false, true,  false, false>, cudaFuncAttributeMaxDynamicSharedMemorySize, SM64);
    cudaFuncSetAttribute(k_step1, cudaFuncAttributeMaxDynamicSharedMemorySize, SMSTEP);

    auto mk = [](const __half* Ahi, const __half* Alo, const __half* Bhi,
                 const __half* Blo, const float* bias, const float* base,
                 float* C, __half* Chi, __half* Clo, int ldc) {
        Ops o; o.Ahi = Ahi; o.Alo = Alo; o.Bhi = Bhi; o.Blo = Blo;
        o.bias = bias; o.base = base; o.C = C; o.Chi = Chi; o.Clo = Clo;
        o.ldc = ldc; return o;
    };

    // fork/join resources (host objects; created and destroyed per call)
    cudaStream_t s2;
    cudaEvent_t e0, e1, e3;
    cudaStreamCreateWithFlags(&s2, cudaStreamNonBlocking);
    cudaEventCreateWithFlags(&e0, cudaEventDisableTiming);
    cudaEventCreateWithFlags(&e1, cudaEventDisableTiming);
    cudaEventCreateWithFlags(&e3, cudaEventDisableTiming);

    // ---- default stream: init + weight splits needed by video GEMM ----
    k_softmax_init<<<1, 256>>>(pscore, state0);
    cudaEventRecord(e0, 0);
    {
        ST4 p;
        p.W[0] = mv_w1; p.hi[0] = mvw1t_hi; p.lo[0] = mvw1t_lo;
        p.W[1] = mv_w2; p.hi[1] = mvw2t_hi; p.lo[1] = mvw2t_lo;
        p.W[2] = mt_w1; p.hi[2] = mtw1t_hi; p.lo[2] = mtw1t_lo;
        p.W[3] = mt_w2; p.hi[3] = mtw2t_hi; p.lo[3] = mtw2t_lo;
        k_splitT4<<<dim3(24, 24, 4), 256>>>(p);
    }
    cudaEventRecord(e1, 0);

    // ---- side stream s2: video + para/question/base branch ----
    cudaStreamWaitEvent(s2, e0, 0);
    k_half<<<(16384 * 768 / 4 + 255) / 256, 256, 0, s2>>>(video, vid_hi, 16384 * 768 / 4);
    {
        G16x3 p;
        p.g[0] = {para,     mt_w1, mt_b1, pparah, 128};
        p.g[1] = {question, mt_w1, mt_b1, pqh,    8};
        p.g[2] = p.g[1];
        k_gemm16z<true><<<dim3(6, 8, 2), 256, 0, s2>>>(p, 768, 768);
    }
    cudaStreamWaitEvent(s2, e1, 0);
    {
        Ops2 o2; o2.o[0] = o2.o[1] = mk(vid_hi, nullptr, mvw1t_hi, nullptr,
                                        mv_b1, nullptr, pseg, nullptr, nullptr, 768);
        k_hmma<128, 1, true, false, false, false, true><<<dim3(6, 128, 1), 256, SM128, s2>>>(o2, 16384, 768, 768);
    }
    {
        G16x3 p;
        p.g[0] = {pparah, mt_w2, mt_b2, pparao, 128};
        p.g[1] = {pqh,    mt_w2, mt_b2, pq,     8};
        p.g[2] = {pseg,   mv_w2, mv_b2, pvpo,   128};
        k_gemm16z<false><<<dim3(6, 8, 3), 256, 0, s2>>>(p, 768, 768);
    }
    k_wsum3<<<dim3(3, 8, 3), 256, 0, s2>>>();
    k_gemm16<false><<<dim3(24, 1), 256, 0, s2>>>(pvpq, mp_w1, mp_b1, pbase, 8, 3072, 2304);
    k_gh<<<18, 128, 0, s2>>>(whh, bhh);
    cudaEventRecord(e3, s2);

    // ---- default stream continues: remaining splits + a-branch HMMA ----
    k_splitT<<<dim3(96, 48), 256>>>(mp_w1 + (size_t)1536 * 3072, mpw1rt_hi, mpw1rt_lo, 1536, 3072);
    k_splitT<<<dim3(24, 96), 256>>>(mp_w2, mpw2t_hi, mpw2t_lo, 3072, 768);
    {
        Split2 p;
        p.in[0] = wih; p.hi[0] = wih_hi; p.lo[0] = wih_lo; p.n4[0] = 2304 * 768 / 4;
        p.in[1] = whh; p.hi[1] = whh_hi; p.lo[1] = whh_lo; p.n4[1] = 2304 * 768 / 4;
        k_split2<<<dim3((2304 * 768 / 4 + 255) / 256, 1, 2), 256>>>(p);
    }
    {
        Split2 p;
        p.in[0] = a_texts;   p.hi[0] = atx_hi; p.lo[0] = atx_lo; p.n4[0] = 1024 * 768 / 4;
        p.in[1] = a_buttons; p.hi[1] = abt_hi; p.lo[1] = abt_lo; p.n4[1] = 1024 * 768 / 4;
        k_split2<<<dim3((1024 * 768 / 4 + 255) / 256, 1, 2), 256>>>(p);
    }
    {
        Ops2 o2;
        o2.o[0] = mk(atx_hi, atx_lo, mtw1t_hi, mtw1t_lo, mt_b1, nullptr,
                     nullptr, tha_hi, tha_lo, 768);
        o2.o[1] = mk(abt_hi, abt_lo, mvw1t_hi, mvw1t_lo, mv_b1, nullptr,
                     nullptr, thb_hi, thb_lo, 768);
        k_hmma<32, 3, true, true, false, false, false><<<dim3(6, 32, 2), 256, SM32>>>(o2, 1024, 768, 768);
    }
    {
        Ops2 o2;
        o2.o[0] = mk(tha_hi, tha_lo, mtw2t_hi, mtw2t_lo, mt_b2, nullptr,
                     nullptr, inpAB_hi, inpAB_lo, 1536);
        o2.o[1] = mk(thb_hi, thb_lo, mvw2t_hi, mvw2t_lo, mv_b2, nullptr,
                     nullptr, inpAB_hi + 768, inpAB_lo + 768, 1536);
        k_hmma<32, 3, false, true, false, false, false><<<dim3(6, 32, 2), 256, SM32>>>(o2, 1024, 768, 768);
    }

    // ---- join: mlp_pre L1 needs base (s2) + inpAB + mpw1rt (default) ----
    cudaStreamWaitEvent(0, e3, 0);
    {
        Ops2 o2; o2.o[0] = o2.o[1] = mk(inpAB_hi, inpAB_lo, mpw1rt_hi, mpw1rt_lo,
                                        pzero, pbase, nullptr, preh_hi, preh_lo, 3072);
        k_hmma<64, 3, true, true, false, true, false><<<dim3(24, 16, 1), 256, SM64>>>(o2, 1024, 3072, 1536);
    }
    {
        Ops2 o2; o2.o[0] = o2.o[1] = mk(preh_hi, preh_lo, mpw2t_hi, mpw2t_lo,
                                        mp_b2, nullptr, px, x_hi, x_lo, 768);
        k_hmma<32, 3, false, true, true, false, false><<<dim3(6, 32, 1), 256, SM32>>>(o2, 1024, 768, 3072);
    }
    {
        Ops2 o2;
        o2.o[0] = mk(x_hi, x_lo, wih_hi, wih_lo, bih, nullptr, pgi, nullptr, nullptr, 2304);
        o2.o[1] = mk(x_hi, x_lo, whh_hi, whh_lo, bhh, nullptr, pghall, nullptr, nullptr, 2304);
        k_hmma<64, 3, false, false, true, false, false><<<dim3(18, 16, 2), 256, SM64>>>(o2, 1024, 2304, 768);
    }

    // sequential scan: 2 launches/step
    for (int s = 0; s < 8; s++) {
        k_step1<<<dim3(6, 8), 256, SMSTEP>>>(s, pr_w1, pr_b1, pr_w2);
        k_step2<<<8, 32>>>(pr_b2, out, s);
    }

    cudaEventDestroy(e0);
    cudaEventDestroy(e1);
    cudaEventDestroy(e3);
    cudaStreamDestroy(s2);
}

// round 12
// speedup vs baseline: 1.1269x; 1.0676x over previous
#include <cuda_runtime.h>
#include <cuda_fp16.h>
#include <math.h>
#include <stdint.h>

// B=8, T=2048, P=16, S=8, A=16, D=768, H=768, 3H=2304, 4D=3072

// ==================== scratch (device globals) ====================
__device__ float g_ps[8 * 16];
__device__ __align__(16) float g_h[8 * 768];
__device__ float g_segmean[128 * 768];
__device__ float g_para_h[128 * 768];
__device__ float g_qh[8 * 768];
__device__ float g_vpre[8 * 768];
__device__ float g_prh[8 * 768];
__device__ float g_vpq[8 * 2304];
__device__ float g_zero[3072];
__device__ float g_base[8 * 3072];
__device__ __align__(128) float g_x[1024 * 768];
__device__ __align__(128) float g_gi[1024 * 2304];
__device__ __align__(128) float g_ghall[1024 * 2304];
__device__ __align__(16) float g_gh[8 * 2304];
__device__ float g_logpart[6 * 128];
__device__ int g_best[8];

// fp16 buffers (hi/lo split)
__device__ __align__(128) __half g_vid_hi[16384 * 768];
__device__ __align__(128) __half g_atx_hi[1024 * 768];
__device__ __align__(128) __half g_atx_lo[1024 * 768];
__device__ __align__(128) __half g_abt_hi[1024 * 768];
__device__ __align__(128) __half g_abt_lo[1024 * 768];
__device__ __align__(128) __half g_wih_hi[2304 * 768];
__device__ __align__(128) __half g_wih_lo[2304 * 768];
__device__ __align__(128) __half g_whh_hi[2304 * 768];
__device__ __align__(128) __half g_whh_lo[2304 * 768];
__device__ __align__(128) __half g_mvw1t_hi[768 * 768];
__device__ __align__(128) __half g_mvw1t_lo[768 * 768];
__device__ __align__(128) __half g_mvw2t_hi[768 * 768];
__device__ __align__(128) __half g_mvw2t_lo[768 * 768];
__device__ __align__(128) __half g_mtw1t_hi[768 * 768];
__device__ __align__(128) __half g_mtw1t_lo[768 * 768];
__device__ __align__(128) __half g_mtw2t_hi[768 * 768];
__device__ __align__(128) __half g_mtw2t_lo[768 * 768];
__device__ __align__(128) __half g_mpw1rt_hi[3072 * 1536];
__device__ __align__(128) __half g_mpw1rt_lo[3072 * 1536];
__device__ __align__(128) __half g_mpw2t_hi[768 * 3072];
__device__ __align__(128) __half g_mpw2t_lo[768 * 3072];
__device__ __align__(128) __half g_tha_hi[1024 * 768];
__device__ __align__(128) __half g_tha_lo[1024 * 768];
__device__ __align__(128) __half g_thb_hi[1024 * 768];
__device__ __align__(128) __half g_thb_lo[1024 * 768];
__device__ __align__(128) __half g_inpAB_hi[1024 * 1536];
__device__ __align__(128) __half g_inpAB_lo[1024 * 1536];
__device__ __align__(128) __half g_preh_hi[1024 * 3072];
__device__ __align__(128) __half g_preh_lo[1024 * 3072];
__device__ __align__(128) __half g_x_hi[1024 * 768];
__device__ __align__(128) __half g_x_lo[1024 * 768];

// ==================== mma.sync helpers ====================
__device__ __forceinline__ void ldm_x4(uint32_t f[4], uint32_t addr) {
    asm volatile("ldmatrix.sync.aligned.m8n8.x4.shared.b16 {%0,%1,%2,%3}, [%4];"
                 : "=r"(f[0]), "=r"(f[1]), "=r"(f[2]), "=r"(f[3]) : "r"(addr));
}
__device__ __forceinline__ void mma16816(float* c, const uint32_t a[4],
                                         uint32_t b0, uint32_t b1) {
    asm volatile(
        "mma.sync.aligned.m16n8k16.row.col.f32.f16.f16.f32 "
        "{%0,%1,%2,%3}, {%4,%5,%6,%7}, {%8,%9}, {%0,%1,%2,%3};"
        : "+f"(c[0]), "+f"(c[1]), "+f"(c[2]), "+f"(c[3])
        : "r"(a[0]), "r"(a[1]), "r"(a[2]), "r"(a[3]), "r"(b0), "r"(b1));
}
#define CP_ASYNC16(dst, src) \
    asm volatile("cp.async.cg.shared.global [%0], [%1], 16;" :: "r"(dst), "l"(src))
#define CP_COMMIT() asm volatile("cp.async.commit_group;")
#define CP_WAIT(n)  asm volatile("cp.async.wait_group %0;" :: "n"(n))

struct Ops {
    const __half *Ahi, *Alo, *Bhi, *Blo;
    const float* bias;
    const float* base;
    float* C;
    __half *Chi, *Clo;
    int ldc;
};
struct Ops2 { Ops o[2]; };

// ==================== HMMA GEMM (proven core) ====================
template <int MT, int NPROD, bool RELU, bool SPLITOUT, bool F32OUT, bool BADD, bool SEG>
__global__ void __launch_bounds__(256, 2) k_hmma(Ops2 ops, int M, int N, int K)
{
    const Ops op = ops.o[blockIdx.z];
    extern __shared__ __align__(128) char smem[];
    const uint32_t s_base = (uint32_t)__cvta_generic_to_shared(smem);
    constexpr int STAGE_BYTES = (MT + 128) * 128;
    constexpr int MI = MT / 32;
    constexpr int KADV = (NPROD == 3) ? 32 : 64;
    constexpr int ACP = MT * 8;

    const int tid = threadIdx.x;
    const int wid = tid >> 5, lane = tid & 31;
    const int wm = wid & 1, wn = wid >> 1;
    const int row0 = blockIdx.y * MT;
    const int col0 = blockIdx.x * 128;
    const int NC = K / KADV;

    float acc[MI][4][4];
    #pragma unroll
    for (int i = 0; i < MI; i++)
        #pragma unroll
        for (int j = 0; j < 4; j++)
            #pragma unroll
            for (int r = 0; r < 4; r++) acc[i][j][r] = 0.f;

    auto load_stage = [&](int c) {
        const int k0 = c * KADV;
        const uint32_t sb = s_base + (uint32_t)((c & 1) * STAGE_BYTES);
        #pragma unroll
        for (int i = tid; i < ACP + 1024; i += 256) {
            const bool isA = i < ACP;
            const int e = isA ? i : i - ACP;
            const int row = e >> 3, ch = e & 7;
            const int grow = (isA ? row0 : col0) + row;
            const __half* src;
            if (NPROD == 3) {
                const int o2 = ch >> 2, kc = ch & 3;
                const __half* base = isA ? (o2 ? op.Alo : op.Ahi) : (o2 ? op.Blo : op.Bhi);
                src = base + (size_t)grow * K + k0 + kc * 8;
            } else {
                src = (isA ? op.Ahi : op.Bhi) + (size_t)grow * K + k0 + ch * 8;
            }
            const uint32_t dst = sb + (uint32_t)((isA ? 0 : MT * 128)
                               + row * 128 + ((ch ^ (row & 7)) << 4));
            CP_ASYNC16(dst, src);
        }
        CP_COMMIT();
    };

    load_stage(0);

    for (int c = 0; c < NC; c++) {
        if (c + 1 < NC) { load_stage(c + 1); CP_WAIT(1); }
        else            { CP_WAIT(0); }
        __syncthreads();

        const uint32_t sA = s_base + (uint32_t)((c & 1) * STAGE_BYTES);
        const uint32_t sB = sA + MT * 128;
        constexpr int NK = (NPROD == 3) ? 2 : 4;

        #pragma unroll
        for (int s = 0; s < NK; s++) {
            uint32_t ah[MI][4], bh[2][4];
            #pragma unroll
            for (int mt = 0; mt < MI; mt++) {
                const int row = wm * (MT / 2) + mt * 16 + (lane & 15);
                const int ch = s * 2 + (lane >> 4);
                ldm_x4(ah[mt], sA + row * 128 + ((ch ^ (row & 7)) << 4));
            }
            #pragma unroll
            for (int ntp = 0; ntp < 2; ntp++) {
                const int row = wn * 32 + ntp * 16 + ((lane >> 4) << 3) + (lane & 7);
                const int ch = s * 2 + ((lane >> 3) & 1);
                ldm_x4(bh[ntp], sB + row * 128 + ((ch ^ (row & 7)) << 4));
            }
            if (NPROD == 3) {
                uint32_t al[MI][4], bl[2][4];
                #pragma unroll
                for (int mt = 0; mt < MI; mt++) {
                    const int row = wm * (MT / 2) + mt * 16 + (lane & 15);
                    const int ch = 4 + s * 2 + (lane >> 4);
                    ldm_x4(al[mt], sA + row * 128 + ((ch ^ (row & 7)) << 4));
                }
                #pragma unroll
                for (int ntp = 0; ntp < 2; ntp++) {
                    const int row = wn * 32 + ntp * 16 + ((lane >> 4) << 3) + (lane & 7);
                    const int ch = 4 + s * 2 + ((lane >> 3) & 1);
                    ldm_x4(bl[ntp], sB + row * 128 + ((ch ^ (row & 7)) << 4));
                }
                #pragma unroll
                for (int mt = 0; mt < MI; mt++)
                    #pragma unroll
                    for (int nt = 0; nt < 4; nt++) {
                        const int p = nt >> 1, q = (nt & 1) * 2;
                        mma16816(acc[mt][nt], ah[mt], bh[p][q], bh[p][q + 1]);
                        mma16816(acc[mt][nt], ah[mt], bl[p][q], bl[p][q + 1]);
                        mma16816(acc[mt][nt], al[mt], bh[p][q], bh[p][q + 1]);
                    }
            } else {
                #pragma unroll
                for (int mt = 0; mt < MI; mt++)
                    #pragma unroll
                    for (int nt = 0; nt < 4; nt++) {
                        const int p = nt >> 1, q = (nt & 1) * 2;
                        mma16816(acc[mt][nt], ah[mt], bh[p][q], bh[p][q + 1]);
                    }
            }
        }
        __syncthreads();
    }

    float csum[4][2];
    if (SEG) {
        #pragma unroll
        for (int nt = 0; nt < 4; nt++) { csum[nt][0] = 0.f; csum[nt][1] = 0.f; }
    }
    #pragma unroll
    for (int mt = 0; mt < MI; mt++) {
        #pragma unroll
        for (int nt = 0; nt < 4; nt++) {
            const int col = col0 + wn * 32 + nt * 8 + (lane & 3) * 2;
            const float2 bv = *reinterpret_cast<const float2*>(op.bias + col);
            #pragma unroll
            for (int half = 0; half < 2; half++) {
                const int grow = row0 + wm * (MT / 2) + mt * 16 + (lane >> 2) + half * 8;
                float v0 = acc[mt][nt][half * 2 + 0] + bv.x;
                float v1 = acc[mt][nt][half * 2 + 1] + bv.y;
                if (BADD) {
                    const float2 bsv = *reinterpret_cast<const float2*>(
                        op.base + (size_t)(grow >> 7) * 3072 + col);
                    v0 += bsv.x; v1 += bsv.y;
                }
                if (RELU) { v0 = fmaxf(v0, 0.f); v1 = fmaxf(v1, 0.f); }
                if (SEG) { csum[nt][0] += v0; csum[nt][1] += v1; }
                if (F32OUT)
                    *reinterpret_cast<float2*>(op.C + (size_t)grow * op.ldc + col) =
                        make_float2(v0, v1);
                if (SPLITOUT) {
                    const __half h0 = __float2half_rn(v0);
                    const __half h1 = __float2half_rn(v1);
                    const __half l0 = __float2half_rn(v0 - __half2float(h0));
                    const __half l1 = __float2half_rn(v1 - __half2float(h1));
                    *reinterpret_cast<__half2*>(op.Chi + (size_t)grow * op.ldc + col) =
                        make_half2(h0, h1);
                    *reinterpret_cast<__half2*>(op.Clo + (size_t)grow * op.ldc + col) =
                        make_half2(l0, l1);
                }
            }
        }
    }
    if (SEG) {
        #pragma unroll
        for (int o = 4; o <= 16; o <<= 1)
            #pragma unroll
            for (int nt = 0; nt < 4; nt++) {
                csum[nt][0] += __shfl_xor_sync(0xffffffffu, csum[nt][0], o);
                csum[nt][1] += __shfl_xor_sync(0xffffffffu, csum[nt][1], o);
            }
        float* scol = reinterpret_cast<float*>(smem);
        if (tid < 128) scol[tid] = 0.f;
        __syncthreads();
        if ((lane >> 2) == 0) {
            #pragma unroll
            for (int nt = 0; nt < 4; nt++) {
                atomicAdd(&scol[wn * 32 + nt * 8 + (lane & 3) * 2 + 0], csum[nt][0]);
                atomicAdd(&scol[wn * 32 + nt * 8 + (lane & 3) * 2 + 1], csum[nt][1]);
            }
        }
        __syncthreads();
        if (tid < 128)
            op.C[(size_t)blockIdx.y * 768 + col0 + tid] = scol[tid] * (1.f / 128.f);
    }
}

// ==================== conversion kernels (batched) ====================
__global__ void k_half(const float* __restrict__ in, __half* __restrict__ hi, int n4) {
    int i = blockIdx.x * 256 + threadIdx.x;
    if (i >= n4) return;
    float4 v = reinterpret_cast<const float4*>(in)[i];
    reinterpret_cast<__half2*>(hi)[i * 2 + 0] =
        make_half2(__float2half_rn(v.x), __float2half_rn(v.y));
    reinterpret_cast<__half2*>(hi)[i * 2 + 1] =
        make_half2(__float2half_rn(v.z), __float2half_rn(v.w));
}

struct Split2 { const float* in[2]; __half* hi[2]; __half* lo[2]; int n4[2]; };
__global__ void k_split2(Split2 p) {
    const int z = blockIdx.z;
    int i = blockIdx.x * 256 + threadIdx.x;
    if (i >= p.n4[z]) return;
    float4 v = reinterpret_cast<const float4*>(p.in[z])[i];
    __half h0 = __float2half_rn(v.x), h1 = __float2half_rn(v.y);
    __half h2 = __float2half_rn(v.z), h3 = __float2half_rn(v.w);
    __half l0 = __float2half_rn(v.x - __half2float(h0));
    __half l1 = __float2half_rn(v.y - __half2float(h1));
    __half l2 = __float2half_rn(v.z - __half2float(h2));
    __half l3 = __float2half_rn(v.w - __half2float(h3));
    reinterpret_cast<__half2*>(p.hi[z])[i * 2 + 0] = make_half2(h0, h1);
    reinterpret_cast<__half2*>(p.hi[z])[i * 2 + 1] = make_half2(h2, h3);
    reinterpret_cast<__half2*>(p.lo[z])[i * 2 + 0] = make_half2(l0, l1);
    reinterpret_cast<__half2*>(p.lo[z])[i * 2 + 1] = make_half2(l2, l3);
}

__global__ void k_splitT(const float* __restrict__ W, __half* __restrict__ hi,
                         __half* __restrict__ lo, int K, int N) {
    __shared__ float t[32][33];
    const int kb = blockIdx.y * 32, nb = blockIdx.x * 32;
    const int tx = threadIdx.x & 31, ty = threadIdx.x >> 5;
    #pragma unroll
    for (int r = ty; r < 32; r += 8)
        t[r][tx] = W[(size_t)(kb + r) * N + nb + tx];
    __syncthreads();
    #pragma unroll
    for (int r = ty; r < 32; r += 8) {
        float v = t[tx][r];
        __half h = __float2half_rn(v);
        __half l = __float2half_rn(v - __half2float(h));
        size_t o = (size_t)(nb + r) * K + kb + tx;
        hi[o] = h;
        lo[o] = l;
    }
}

struct ST4 { const float* W[4]; __half* hi[4]; __half* lo[4]; };
__global__ void k_splitT4(ST4 p) {
    const int z = blockIdx.z;
    __shared__ float t[32][33];
    const int kb = blockIdx.y * 32, nb = blockIdx.x * 32;
    const int tx = threadIdx.x & 31, ty = threadIdx.x >> 5;
    #pragma unroll
    for (int r = ty; r < 32; r += 8)
        t[r][tx] = p.W[z][(size_t)(kb + r) * 768 + nb + tx];
    __syncthreads();
    #pragma unroll
    for (int r = ty; r < 32; r += 8) {
        float v = t[tx][r];
        __half h = __float2half_rn(v);
        __half l = __float2half_rn(v - __half2float(h));
        size_t o = (size_t)(nb + r) * 768 + kb + tx;
        p.hi[z][o] = h;
        p.lo[z][o] = l;
    }
}

// ==================== fp32 helper kernels ====================
__global__ void k_softmax_init(const float* __restrict__ scores,
                               const float* __restrict__ state0) {
    int tid = threadIdx.x;
    int warp = tid >> 5, lane = tid & 31;
    if (warp < 8) {
        float v = (lane < 16) ? scores[warp * 16 + lane] : -1e30f;
        float m = v;
        #pragma unroll
        for (int o = 16; o > 0; o >>= 1) m = fmaxf(m, __shfl_xor_sync(0xffffffffu, m, o));
        float e = (lane < 16) ? expf(v - m) : 0.f;
        float s = e;
        #pragma unroll
        for (int o = 16; o > 0; o >>= 1) s += __shfl_xor_sync(0xffffffffu, s, o);
        if (lane < 16) g_ps[warp * 16 + lane] = e / s;
    }
    for (int i = tid; i < 8 * 768; i += blockDim.x) g_h[i] = state0[i % 768];
    for (int i = tid; i < 3072; i += blockDim.x) g_zero[i] = 0.f;
}

template <bool RELU>
__global__ void __launch_bounds__(256) k_gemm16(
    const float* __restrict__ A, const float* __restrict__ W,
    const float* __restrict__ bias, float* __restrict__ C,
    int M, int N, int K) {
    __shared__ __align__(16) float As[32][16];
    __shared__ __align__(16) float Ws[32][128];
    const int tid = threadIdx.x;
    const int row0 = blockIdx.y * 16;
    const int col0 = blockIdx.x * 128;
    const int row = tid >> 4;
    const int cg = tid & 15;
    float acc[8];
    #pragma unroll
    for (int j = 0; j < 8; j++) acc[j] = 0.f;
    for (int k0 = 0; k0 < K; k0 += 32) {
        if (tid < 128) {
            int ar = tid >> 3, ac = (tid & 7) * 4;
            float4 av = make_float4(0.f, 0.f, 0.f, 0.f);
            int gr = row0 + ar;
            if (gr < M) av = *reinterpret_cast<const float4*>(A + (size_t)gr * K + k0 + ac);
            As[ac + 0][ar] = av.x; As[ac + 1][ar] = av.y;
            As[ac + 2][ar] = av.z; As[ac + 3][ar] = av.w;
        }
        #pragma unroll
        for (int j = 0; j < 4; j++) {
            int wr = (tid >> 5) + j * 8;
            int wc = (tid & 31) * 4;
            float4 wv = *reinterpret_cast<const float4*>(W + (size_t)(k0 + wr) * N + col0 + wc);
            *reinterpret_cast<float4*>(&Ws[wr][wc]) = wv;
        }
        __syncthreads();
        #pragma unroll
        for (int k = 0; k < 32; k++) {
            float a = As[k][row];
            float4 b0 = *reinterpret_cast<const float4*>(&Ws[k][cg * 4]);
            float4 b1 = *reinterpret_cast<const float4*>(&Ws[k][64 + cg * 4]);
            acc[0] = fmaf(a, b0.x, acc[0]); acc[1] = fmaf(a, b0.y, acc[1]);
            acc[2] = fmaf(a, b0.z, acc[2]); acc[3] = fmaf(a, b0.w, acc[3]);
            acc[4] = fmaf(a, b1.x, acc[4]); acc[5] = fmaf(a, b1.y, acc[5]);
            acc[6] = fmaf(a, b1.z, acc[6]); acc[7] = fmaf(a, b1.w, acc[7]);
        }
        __syncthreads();
    }
    int r = row0 + row;
    if (r < M) {
        float4 bv0 = *reinterpret_cast<const float4*>(bias + col0 + cg * 4);
        float4 bv1 = *reinterpret_cast<const float4*>(bias + col0 + 64 + cg * 4);
        float o[8];
        o[0] = acc[0] + bv0.x; o[1] = acc[1] + bv0.y;
        o[2] = acc[2] + bv0.z; o[3] = acc[3] + bv0.w;
        o[4] = acc[4] + bv1.x; o[5] = acc[5] + bv1.y;
        o[6] = acc[6] + bv1.z; o[7] = acc[7] + bv1.w;
        if (RELU) {
            #pragma unroll
            for (int j = 0; j < 8; j++) o[j] = fmaxf(o[j], 0.f);
        }
        *reinterpret_cast<float4*>(C + (size_t)r * N + col0 + cg * 4) =
            make_float4(o[0], o[1], o[2], o[3]);
        *reinterpret_cast<float4*>(C + (size_t)r * N + col0 + 64 + cg * 4) =
            make_float4(o[4], o[5], o[6], o[7]);
    }
}

// z-batched fp32 GEMM with output ldc (so it can scatter into vpq columns)
struct G16 { const float* A; const float* W; const float* bias; float* C; int M; int ldc; };
struct G16x3 { G16 g[3]; };
template <bool RELU>
__global__ void __launch_bounds__(256) k_gemm16z(G16x3 p, int N, int K) {
    const G16 gz = p.g[blockIdx.z];
    const int row0 = blockIdx.y * 16;
    if (row0 >= gz.M) return;
    __shared__ __align__(16) float As[32][16];
    __shared__ __align__(16) float Ws[32][128];
    const int tid = threadIdx.x;
    const int col0 = blockIdx.x * 128;
    const int row = tid >> 4;
    const int cg = tid & 15;
    float acc[8];
    #pragma unroll
    for (int j = 0; j < 8; j++) acc[j] = 0.f;
    for (int k0 = 0; k0 < K; k0 += 32) {
        if (tid < 128) {
            int ar = tid >> 3, ac = (tid & 7) * 4;
            float4 av = make_float4(0.f, 0.f, 0.f, 0.f);
            int gr = row0 + ar;
            if (gr < gz.M) av = *reinterpret_cast<const float4*>(gz.A + (size_t)gr * K + k0 + ac);
            As[ac + 0][ar] = av.x; As[ac + 1][ar] = av.y;
            As[ac + 2][ar] = av.z; As[ac + 3][ar] = av.w;
        }
        #pragma unroll
        for (int j = 0; j < 4; j++) {
            int wr = (tid >> 5) + j * 8;
            int wc = (tid & 31) * 4;
            float4 wv = *reinterpret_cast<const float4*>(gz.W + (size_t)(k0 + wr) * N + col0 + wc);
            *reinterpret_cast<float4*>(&Ws[wr][wc]) = wv;
        }
        __syncthreads();
        #pragma unroll
        for (int k = 0; k < 32; k++) {
            float a = As[k][row];
            float4 b0 = *reinterpret_cast<const float4*>(&Ws[k][cg * 4]);
            float4 b1 = *reinterpret_cast<const float4*>(&Ws[k][64 + cg * 4]);
            acc[0] = fmaf(a, b0.x, acc[0]); acc[1] = fmaf(a, b0.y, acc[1]);
            acc[2] = fmaf(a, b0.z, acc[2]); acc[3] = fmaf(a, b0.w, acc[3]);
            acc[4] = fmaf(a, b1.x, acc[4]); acc[5] = fmaf(a, b1.y, acc[5]);
            acc[6] = fmaf(a, b1.z, acc[6]); acc[7] = fmaf(a, b1.w, acc[7]);
        }
        __syncthreads();
    }
    int r = row0 + row;
    if (r < gz.M) {
        float4 bv0 = *reinterpret_cast<const float4*>(gz.bias + col0 + cg * 4);
        float4 bv1 = *reinterpret_cast<const float4*>(gz.bias + col0 + 64 + cg * 4);
        float o[8];
        o[0] = acc[0] + bv0.x; o[1] = acc[1] + bv0.y;
        o[2] = acc[2] + bv0.z; o[3] = acc[3] + bv0.w;
        o[4] = acc[4] + bv1.x; o[5] = acc[5] + bv1.y;
        o[6] = acc[6] + bv1.z; o[7] = acc[7] + bv1.w;
        if (RELU) {
            #pragma unroll
            for (int j = 0; j < 8; j++) o[j] = fmaxf(o[j], 0.f);
        }
        *reinterpret_cast<float4*>(gz.C + (size_t)r * gz.ldc + col0 + cg * 4) =
            make_float4(o[0], o[1], o[2], o[3]);
        *reinterpret_cast<float4*>(gz.C + (size_t)r * gz.ldc + col0 + 64 + cg * 4) =
            make_float4(o[4], o[5], o[6], o[7]);
    }
}

// z0: vpre = ps @ segmean; z1: prh = ps @ para_h
__global__ void k_wsum2() {
    const int z = blockIdx.z;
    const int b = blockIdx.y;
    const int d = blockIdx.x * 256 + threadIdx.x;
    const float* in = (z == 0) ? g_segmean : g_para_h;
    float* outp = (z == 0) ? g_vpre : g_prh;
    float acc = 0.f;
    #pragma unroll
    for (int p = 0; p < 16; p++)
        acc = fmaf(g_ps[b * 16 + p], in[(size_t)(b * 16 + p) * 768 + d], acc);
    outp[b * 768 + d] = acc;
}

__global__ void __launch_bounds__(128) k_gh(const float* __restrict__ whh,
                                            const float* __restrict__ bhh) {
    __shared__ float hs[8 * 768];
    for (int i = threadIdx.x; i < 8 * 768; i += 128) hs[i] = g_h[i];
    __syncthreads();
    int n = blockIdx.x * 128 + threadIdx.x;
    float bv = bhh[n];
    float acc[8];
    #pragma unroll
    for (int b = 0; b < 8; b++) acc[b] = bv;
    const float4* wr = reinterpret_cast<const float4*>(whh + (size_t)n * 768);
    #pragma unroll 4
    for (int k4 = 0; k4 < 192; k4++) {
        float4 w = wr[k4];
        int kb = k4 * 4;
        #pragma unroll
        for (int b = 0; b < 8; b++) {
            const float* hb = hs + b * 768 + kb;
            acc[b] = fmaf(w.x, hb[0], fmaf(w.y, hb[1], fmaf(w.z, hb[2], fmaf(w.w, hb[3], acc[b]))));
        }
    }
    #pragma unroll
    for (int b = 0; b < 8; b++) g_gh[b * 2304 + n] = acc[b];
}

// ==================== fused scan step 1 ====================
__global__ void __launch_bounds__(256) k_step1(
    int s, const float* __restrict__ w1, const float* __restrict__ b1,
    const float* __restrict__ w2)
{
    extern __shared__ float dsm[];
    float* st = dsm;
    float* Ws = dsm + 16 * 768;
    const int tid = threadIdx.x;
    const int row0 = blockIdx.y * 16;
    const int col0 = blockIdx.x * 128;

    for (int idx = tid; idx < 16 * 768; idx += 256) {
        const int rr = idx / 768, hh = idx - rr * 768;
        const int r = row0 + rr;
        const int b = r >> 4, a = r & 15;
        const size_t gib = (size_t)((b * 8 + s) * 16 + a) * 2304;
        const float* ghrow;
        const float* hprev;
        if (s == 0) {
            ghrow = g_gh + b * 2304;
            hprev = g_h + b * 768;
        } else {
            const int prev = (b * 8 + (s - 1)) * 16 + g_best[b];
            ghrow = g_ghall + (size_t)prev * 2304;
            hprev = g_x + (size_t)prev * 768;
        }
        const float ir = g_gi[gib + hh];
        const float iz = g_gi[gib + 768 + hh];
        const float in_ = g_gi[gib + 1536 + hh];
        const float rr_ = 1.f / (1.f + expf(-(ir + ghrow[hh])));
        const float zz = 1.f / (1.f + expf(-(iz + ghrow[768 + hh])));
        const float nn = tanhf(in_ + rr_ * ghrow[1536 + hh]);
        st[rr * 768 + hh] = (1.f - zz) * nn + zz * hprev[hh];
    }
    __syncthreads();

    const int row = tid >> 4, cg = tid & 15;
    float acc[8];
    #pragma unroll
    for (int j = 0; j < 8; j++) acc[j] = 0.f;
    for (int k0 = 0; k0 < 768; k0 += 32) {
        #pragma unroll
        for (int j = 0; j < 4; j++) {
            const int wr = (tid >> 5) + j * 8;
            const int wc = (tid & 31) * 4;
            *reinterpret_cast<float4*>(&Ws[wr * 128 + wc]) =
                *reinterpret_cast<const float4*>(w1 + (size_t)(k0 + wr) * 768 + col0 + wc);
        }
        __syncthreads();
        #pragma unroll
        for (int k = 0; k < 32; k++) {
            const float a = st[row * 768 + k0 + k];
            const float4 b0 = *reinterpret_cast<const float4*>(&Ws[k * 128 + cg * 4]);
            const float4 b1v = *reinterpret_cast<const float4*>(&Ws[k * 128 + 64 + cg * 4]);
            acc[0] = fmaf(a, b0.x, acc[0]); acc[1] = fmaf(a, b0.y, acc[1]);
            acc[2] = fmaf(a, b0.z, acc[2]); acc[3] = fmaf(a, b0.w, acc[3]);
            acc[4] = fmaf(a, b1v.x, acc[4]); acc[5] = fmaf(a, b1v.y, acc[5]);
            acc[6] = fmaf(a, b1v.z, acc[6]); acc[7] = fmaf(a, b1v.w, acc[7]);
        }
        __syncthreads();
    }

    const float4 bv0 = *reinterpret_cast<const float4*>(b1 + col0 + cg * 4);
    const float4 bv1 = *reinterpret_cast<const float4*>(b1 + col0 + 64 + cg * 4);
    const float4 w20 = *reinterpret_cast<const float4*>(w2 + col0 + cg * 4);
    const float4 w21 = *reinterpret_cast<const float4*>(w2 + col0 + 64 + cg * 4);
    float part = 0.f;
    part += fmaxf(acc[0] + bv0.x, 0.f) * w20.x;
    part += fmaxf(acc[1] + bv0.y, 0.f) * w20.y;
    part += fmaxf(acc[2] + bv0.z, 0.f) * w20.z;
    part += fmaxf(acc[3] + bv0.w, 0.f) * w20.w;
    part += fmaxf(acc[4] + bv1.x, 0.f) * w21.x;
    part += fmaxf(acc[5] + bv1.y, 0.f) * w21.y;
    part += fmaxf(acc[6] + bv1.z, 0.f) * w21.z;
    part += fmaxf(acc[7] + bv1.w, 0.f) * w21.w;
    #pragma unroll
    for (int off = 1; off < 16; off <<= 1)
        part += __shfl_xor_sync(0xffffffffu, part, off);
    if (cg == 0)
        g_logpart[blockIdx.x * 128 + row0 + row] = part;
}

__global__ void k_step2(const float* __restrict__ b2, float* __restrict__ out, int s) {
    const int b = blockIdx.x;
    const int lane = threadIdx.x;
    float val = -1e30f;
    int idx = 1000;
    if (lane < 16) {
        float lg = b2[0];
        #pragma unroll
        for (int x = 0; x < 6; x++) lg += g_logpart[x * 128 + b * 16 + lane];
        out[(b * 8 + s) * 16 + lane] = lg;
        val = lg;
        idx = lane;
    }
    #pragma unroll
    for (int off = 8; off > 0; off >>= 1) {
        const float oval = __shfl_down_sync(0xffffffffu, val, off);
        const int oidx = __shfl_down_sync(0xffffffffu, idx, off);
        if (oval > val || (oval == val && oidx < idx)) { val = oval; idx = oidx; }
    }
    if (lane == 0) g_best[b] = idx;
}

// ==================== host ====================
#define GETSYM(p, s) cudaGetSymbolAddress((void**)&(p), s)

extern "C" void kernel_launch(void* const* d_in, const int* in_sizes, int n_in,
                              void* d_out, int out_size) {
    (void)in_sizes; (void)n_in; (void)out_size;
    const float* video     = (const float*)d_in[0];
    const float* para      = (const float*)d_in[1];
    const float* question  = (const float*)d_in[2];
    const float* pscore    = (const float*)d_in[3];
    const float* a_texts   = (const float*)d_in[4];
    const float* a_buttons = (const float*)d_in[5];
    const float* mv_w1 = (const float*)d_in[6],  *mv_b1 = (const float*)d_in[7];
    const float* mv_w2 = (const float*)d_in[8],  *mv_b2 = (const float*)d_in[9];
    const float* mt_w1 = (const float*)d_in[10], *mt_b1 = (const float*)d_in[11];
    const float* mt_w2 = (const float*)d_in[12], *mt_b2 = (const float*)d_in[13];
    const float* mp_w1 = (const float*)d_in[14], *mp_b1 = (const float*)d_in[15];
    const float* mp_w2 = (const float*)d_in[16], *mp_b2 = (const float*)d_in[17];
    const float* wih   = (const float*)d_in[18], *bih   = (const float*)d_in[19];
    const float* whh   = (const float*)d_in[20], *bhh   = (const float*)d_in[21];
    const float* pr_w1 = (const float*)d_in[22], *pr_b1 = (const float*)d_in[23];
    const float* pr_w2 = (const float*)d_in[24], *pr_b2 = (const float*)d_in[25];
    const float* state0 = (const float*)d_in[26];
    float* out = (float*)d_out;

    float *pseg, *pparah, *pqh, *pvpre, *pprh;
    float *pvpq, *pzero, *pbase, *px, *pgi, *pghall;
    GETSYM(pseg, g_segmean); GETSYM(pparah, g_para_h); GETSYM(pqh, g_qh);
    GETSYM(pvpre, g_vpre); GETSYM(pprh, g_prh);
    GETSYM(pvpq, g_vpq); GETSYM(pzero, g_zero); GETSYM(pbase, g_base);
    GETSYM(px, g_x); GETSYM(pgi, g_gi); GETSYM(pghall, g_ghall);

    __half *vid_hi, *atx_hi, *atx_lo, *abt_hi, *abt_lo;
    __half *wih_hi, *wih_lo, *whh_hi, *whh_lo;
    __half *mvw1t_hi, *mvw1t_lo, *mvw2t_hi, *mvw2t_lo, *mtw1t_hi, *mtw1t_lo;
    __half *mtw2t_hi, *mtw2t_lo, *mpw1rt_hi, *mpw1rt_lo, *mpw2t_hi, *mpw2t_lo;
    __half *tha_hi, *tha_lo, *thb_hi, *thb_lo, *inpAB_hi, *inpAB_lo;
    __half *preh_hi, *preh_lo, *x_hi, *x_lo;
    GETSYM(vid_hi, g_vid_hi);
    GETSYM(atx_hi, g_atx_hi); GETSYM(atx_lo, g_atx_lo);
    GETSYM(abt_hi, g_abt_hi); GETSYM(abt_lo, g_abt_lo);
    GETSYM(wih_hi, g_wih_hi); GETSYM(wih_lo, g_wih_lo);
    GETSYM(whh_hi, g_whh_hi); GETSYM(whh_lo, g_whh_lo);
    GETSYM(mvw1t_hi, g_mvw1t_hi); GETSYM(mvw1t_lo, g_mvw1t_lo);
    GETSYM(mvw2t_hi, g_mvw2t_hi); GETSYM(mvw2t_lo, g_mvw2t_lo);
    GETSYM(mtw1t_hi, g_mtw1t_hi); GETSYM(mtw1t_lo, g_mtw1t_lo);
    GETSYM(mtw2t_hi, g_mtw2t_hi); GETSYM(mtw2t_lo, g_mtw2t_lo);
    GETSYM(mpw1rt_hi, g_mpw1rt_hi); GETSYM(mpw1rt_lo, g_mpw1rt_lo);
    GETSYM(mpw2t_hi, g_mpw2t_hi); GETSYM(mpw2t_lo, g_mpw2t_lo);
    GETSYM(tha_hi, g_tha_hi); GETSYM(tha_lo, g_tha_lo);
    GETSYM(thb_hi, g_thb_hi); GETSYM(thb_lo, g_thb_lo);
    GETSYM(inpAB_hi, g_inpAB_hi); GETSYM(inpAB_lo, g_inpAB_lo);
    GETSYM(preh_hi, g_preh_hi); GETSYM(preh_lo, g_preh_lo);
    GETSYM(x_hi, g_x_hi); GETSYM(x_lo, g_x_lo);

    constexpr int SM128 = (128 + 128) * 128 * 2;
    constexpr int SM64  = (64 + 128) * 128 * 2;
    constexpr int SM32  = (32 + 128) * 128 * 2;
    constexpr int SMSTEP = 16 * 768 * 4 + 32 * 128 * 4;
    cudaFuncSetAttribute(k_hmma<128, 1, true,  false, false, false, true >, cudaFuncAttributeMaxDynamicSharedMemorySize, SM128);
    cudaFuncSetAttribute(k_hmma<32,  3, true,  true,  false, false, false>, cudaFuncAttributeMaxDynamicSharedMemorySize, SM32);
    cudaFuncSetAttribute(k_hmma<32,  3, false, true,  false, false, false>, cudaFuncAttributeMaxDynamicSharedMemorySize, SM32);
    cudaFuncSetAttribute(k_hmma<64,  3, true,  true,  false, true,  false>, cudaFuncAttributeMaxDynamicSharedMemorySize, SM64);
    cudaFuncSetAttribute(k_hmma<32,  3, false, true,  true,  false, false>, cudaFuncAttributeMaxDynamicSharedMemorySize, SM32);
    cudaFuncSetAttribute(k_hmma<64,  3, false, false, true,  false, false>, cudaFuncAttributeMaxDynamicSharedMemorySize, SM64);
    cudaFuncSetAttribute(k_step1, cudaFuncAttributeMaxDynamicSharedMemorySize, SMSTEP);

    auto mk = [](const __half* Ahi, const __half* Alo, const __half* Bhi,
                 const __half* Blo, const float* bias, const float* base,
                 float* C, __half* Chi, __half* Clo, int ldc) {
        Ops o; o.Ahi = Ahi; o.Alo = Alo; o.Bhi = Bhi; o.Blo = Blo;
        o.bias = bias; o.base = base; o.C = C; o.Chi = Chi; o.Clo = Clo;
        o.ldc = ldc; return o;
    };

    cudaStream_t s2;
    cudaEvent_t e0, e1, epq, e3;
    cudaStreamCreateWithFlags(&s2, cudaStreamNonBlocking);
    cudaEventCreateWithFlags(&e0, cudaEventDisableTiming);
    cudaEventCreateWithFlags(&e1, cudaEventDisableTiming);
    cudaEventCreateWithFlags(&epq, cudaEventDisableTiming);
    cudaEventCreateWithFlags(&e3, cudaEventDisableTiming);

    // ---- default: init + weight splits + para/question L1 ----
    k_softmax_init<<<1, 256>>>(pscore, state0);
    cudaEventRecord(e0, 0);
    {
        ST4 p;
        p.W[0] = mv_w1; p.hi[0] = mvw1t_hi; p.lo[0] = mvw1t_lo;
        p.W[1] = mv_w2; p.hi[1] = mvw2t_hi; p.lo[1] = mvw2t_lo;
        p.W[2] = mt_w1; p.hi[2] = mtw1t_hi; p.lo[2] = mtw1t_lo;
        p.W[3] = mt_w2; p.hi[3] = mtw2t_hi; p.lo[3] = mtw2t_lo;
        k_splitT4<<<dim3(24, 24, 4), 256>>>(p);
    }
    cudaEventRecord(e1, 0);
    {
        G16x3 p;
        p.g[0] = {para,     mt_w1, mt_b1, pparah, 128, 768};
        p.g[1] = {question, mt_w1, mt_b1, pqh,    8,   768};
        p.g[2] = p.g[1];
        k_gemm16z<true><<<dim3(6, 8, 2), 256>>>(p, 768, 768);
    }
    cudaEventRecord(epq, 0);

    // ---- s2: video conversion + GEMM + wsum + tiny L2 + base + gh ----
    cudaStreamWaitEvent(s2, e0, 0);
    k_half<<<(16384 * 768 / 4 + 255) / 256, 256, 0, s2>>>(video, vid_hi, 16384 * 768 / 4);
    k_gh<<<18, 128, 0, s2>>>(whh, bhh);
    cudaStreamWaitEvent(s2, e1, 0);
    {
        Ops2 o2; o2.o[0] = o2.o[1] = mk(vid_hi, nullptr, mvw1t_hi, nullptr,
                                        mv_b1, nullptr, pseg, nullptr, nullptr, 768);
        k_hmma<128, 1, true, false, false, false, true><<<dim3(6, 128, 1), 256, SM128, s2>>>(o2, 16384, 768, 768);
    }
    cudaStreamWaitEvent(s2, epq, 0);
    k_wsum2<<<dim3(3, 8, 2), 256, 0, s2>>>();
    {   // vp, pr, q (all M=8) written straight into vpq columns
        G16x3 p;
        p.g[0] = {pvpre, mv_w2, mv_b2, pvpq + 0,    8, 2304};
        p.g[1] = {pprh,  mt_w2, mt_b2, pvpq + 768,  8, 2304};
        p.g[2] = {pqh,   mt_w2, mt_b2, pvpq + 1536, 8, 2304};
        k_gemm16z<false><<<dim3(6, 1, 3), 256, 0, s2>>>(p, 768, 768);
    }
    k_gemm16<false><<<dim3(24, 1), 256, 0, s2>>>(pvpq, mp_w1, mp_b1, pbase, 8, 3072, 2304);
    cudaEventRecord(e3, s2);

    // ---- default: remaining splits + a-branch HMMA ----
    k_splitT<<<dim3(96, 48), 256>>>(mp_w1 + (size_t)1536 * 3072, mpw1rt_hi, mpw1rt_lo, 1536, 3072);
    k_splitT<<<dim3(24, 96), 256>>>(mp_w2, mpw2t_hi, mpw2t_lo, 3072, 768);
    {
        Split2 p;
        p.in[0] = wih; p.hi[0] = wih_hi; p.lo[0] = wih_lo; p.n4[0] = 2304 * 768 / 4;
        p.in[1] = whh; p.hi[1] = whh_hi; p.lo[1] = whh_lo; p.n4[1] = 2304 * 768 / 4;
        k_split2<<<dim3((2304 * 768 / 4 + 255) / 256, 1, 2), 256>>>(p);
    }
    {
        Split2 p;
        p.in[0] = a_texts;   p.hi[0] = atx_hi; p.lo[0] = atx_lo; p.n4[0] = 1024 * 768 / 4;
        p.in[1] = a_buttons; p.hi[1] = abt_hi; p.lo[1] = abt_lo; p.n4[1] = 1024 * 768 / 4;
        k_split2<<<dim3((1024 * 768 / 4 + 255) / 256, 1, 2), 256>>>(p);
    }
    {
        Ops2 o2;
        o2.o[0] = mk(atx_hi, atx_lo, mtw1t_hi, mtw1t_lo, mt_b1, nullptr,
                     nullptr, tha_hi, tha_lo, 768);
        o2.o[1] = mk(abt_hi, abt_lo, mvw1t_hi, mvw1t_lo, mv_b1, nullptr,
                     nullptr, thb_hi, thb_lo, 768);
        k_hmma<32, 3, true, true, false, false, false><<<dim3(6, 32, 2), 256, SM32>>>(o2, 1024, 768, 768);
    }
    {
        Ops2 o2;
        o2.o[0] = mk(tha_hi, tha_lo, mtw2t_hi, mtw2t_lo, mt_b2, nullptr,
                     nullptr, inpAB_hi, inpAB_lo, 1536);
        o2.o[1] = mk(thb_hi, thb_lo, mvw2t_hi, mvw2t_lo, mv_b2, nullptr,
                     nullptr, inpAB_hi + 768, inpAB_lo + 768, 1536);
        k_hmma<32, 3, false, true, false, false, false><<<dim3(6, 32, 2), 256, SM32>>>(o2, 1024, 768, 768);
    }

    // ---- join ----
    cudaStreamWaitEvent(0, e3, 0);
    {
        Ops2 o2; o2.o[0] = o2.o[1] = mk(inpAB_hi, inpAB_lo, mpw1rt_hi, mpw1rt_lo,
                                        pzero, pbase, nullptr, preh_hi, preh_lo, 3072);
        k_hmma<64, 3, true, true, false, true, false><<<dim3(24, 16, 1), 256, SM64>>>(o2, 1024, 3072, 1536);
    }
    {
        Ops2 o2; o2.o[0] = o2.o[1] = mk(preh_hi, preh_lo, mpw2t_hi, mpw2t_lo,
                                        mp_b2, nullptr, px, x_hi, x_lo, 768);
        k_hmma<32, 3, false, true, true, false, false><<<dim3(6, 32, 1), 256, SM32>>>(o2, 1024, 768, 3072);
    }
    {
        Ops2 o2;
        o2.o[0] = mk(x_hi, x_lo, wih_hi, wih_lo, bih, nullptr, pgi, nullptr, nullptr, 2304);
        o2.o[1] = mk(x_hi, x_lo, whh_hi, whh_lo, bhh, nullptr, pghall, nullptr, nullptr, 2304);
        k_hmma<64, 3, false, false, true, false, false><<<dim3(18, 16, 2), 256, SM64>>>(o2, 1024, 2304, 768);
    }

    // sequential scan
    for (int s = 0; s < 8; s++) {
        k_step1<<<dim3(6, 8), 256, SMSTEP>>>(s, pr_w1, pr_b1, pr_w2);
        k_step2<<<8, 32>>>(pr_b2, out, s);
    }

    cudaEventDestroy(e0);
    cudaEventDestroy(e1);
    cudaEventDestroy(epq);
    cudaEventDestroy(e3);
    cudaStreamDestroy(s2);
}

// round 13
// speedup vs baseline: 1.1593x; 1.0287x over previous
#include <cuda_runtime.h>
#include <cuda_fp16.h>
#include <math.h>
#include <stdint.h>

// B=8, T=2048, P=16, S=8, A=16, D=768, H=768, 3H=2304, 4D=3072

// ==================== scratch (device globals) ====================
__device__ float g_ps[8 * 16];
__device__ __align__(16) float g_h[8 * 768];
__device__ float g_segmean[128 * 768];
__device__ float g_para_h[128 * 768];
__device__ float g_qh[8 * 768];
__device__ float g_vpre[8 * 768];
__device__ float g_prh[8 * 768];
__device__ float g_vpq[8 * 2304];
__device__ float g_zero[3072];
__device__ float g_base[8 * 3072];
__device__ __align__(128) float g_x[1024 * 768];
__device__ __align__(128) float g_gi[1024 * 2304];
__device__ __align__(128) float g_ghall[1024 * 2304];
__device__ __align__(16) float g_gh[8 * 2304];
__device__ float g_logpart[6 * 128];
__device__ int g_best[8];

// fp16 buffers (hi/lo split)
__device__ __align__(128) __half g_vid_hi[16384 * 768];
__device__ __align__(128) __half g_atx_hi[1024 * 768];
__device__ __align__(128) __half g_atx_lo[1024 * 768];
__device__ __align__(128) __half g_abt_hi[1024 * 768];
__device__ __align__(128) __half g_abt_lo[1024 * 768];
__device__ __align__(128) __half g_wih_hi[2304 * 768];
__device__ __align__(128) __half g_wih_lo[2304 * 768];
__device__ __align__(128) __half g_whh_hi[2304 * 768];
__device__ __align__(128) __half g_whh_lo[2304 * 768];
__device__ __align__(128) __half g_mvw1t_hi[768 * 768];
__device__ __align__(128) __half g_mvw1t_lo[768 * 768];
__device__ __align__(128) __half g_mvw2t_hi[768 * 768];
__device__ __align__(128) __half g_mvw2t_lo[768 * 768];
__device__ __align__(128) __half g_mtw1t_hi[768 * 768];
__device__ __align__(128) __half g_mtw1t_lo[768 * 768];
__device__ __align__(128) __half g_mtw2t_hi[768 * 768];
__device__ __align__(128) __half g_mtw2t_lo[768 * 768];
__device__ __align__(128) __half g_mpw1rt_hi[3072 * 1536];
__device__ __align__(128) __half g_mpw1rt_lo[3072 * 1536];
__device__ __align__(128) __half g_mpw2t_hi[768 * 3072];
__device__ __align__(128) __half g_mpw2t_lo[768 * 3072];
__device__ __align__(128) __half g_tha_hi[1024 * 768];
__device__ __align__(128) __half g_tha_lo[1024 * 768];
__device__ __align__(128) __half g_thb_hi[1024 * 768];
__device__ __align__(128) __half g_thb_lo[1024 * 768];
__device__ __align__(128) __half g_inpAB_hi[1024 * 1536];
__device__ __align__(128) __half g_inpAB_lo[1024 * 1536];
__device__ __align__(128) __half g_preh_hi[1024 * 3072];
__device__ __align__(128) __half g_preh_lo[1024 * 3072];
__device__ __align__(128) __half g_x_hi[1024 * 768];
__device__ __align__(128) __half g_x_lo[1024 * 768];

// ==================== mma.sync helpers ====================
__device__ __forceinline__ void ldm_x4(uint32_t f[4], uint32_t addr) {
    asm volatile("ldmatrix.sync.aligned.m8n8.x4.shared.b16 {%0,%1,%2,%3}, [%4];"
                 : "=r"(f[0]), "=r"(f[1]), "=r"(f[2]), "=r"(f[3]) : "r"(addr));
}
__device__ __forceinline__ void mma16816(float* c, const uint32_t a[4],
                                         uint32_t b0, uint32_t b1) {
    asm volatile(
        "mma.sync.aligned.m16n8k16.row.col.f32.f16.f16.f32 "
        "{%0,%1,%2,%3}, {%4,%5,%6,%7}, {%8,%9}, {%0,%1,%2,%3};"
        : "+f"(c[0]), "+f"(c[1]), "+f"(c[2]), "+f"(c[3])
        : "r"(a[0]), "r"(a[1]), "r"(a[2]), "r"(a[3]), "r"(b0), "r"(b1));
}
#define CP_ASYNC16(dst, src) \
    asm volatile("cp.async.cg.shared.global [%0], [%1], 16;" :: "r"(dst), "l"(src))
#define CP_COMMIT() asm volatile("cp.async.commit_group;")
#define CP_WAIT(n)  asm volatile("cp.async.wait_group %0;" :: "n"(n))

struct Ops {
    const __half *Ahi, *Alo, *Bhi, *Blo;
    const float* bias;
    const float* base;
    float* C;
    __half *Chi, *Clo;
    int ldc;
};
struct Ops2 { Ops o[2]; };

// ==================== HMMA GEMM (proven core) ====================
template <int MT, int NPROD, bool RELU, bool SPLITOUT, bool F32OUT, bool BADD, bool SEG>
__global__ void __launch_bounds__(256, 2) k_hmma(Ops2 ops, int M, int N, int K)
{
    const Ops op = ops.o[blockIdx.z];
    extern __shared__ __align__(128) char smem[];
    const uint32_t s_base = (uint32_t)__cvta_generic_to_shared(smem);
    constexpr int STAGE_BYTES = (MT + 128) * 128;
    constexpr int MI = MT / 32;
    constexpr int KADV = (NPROD == 3) ? 32 : 64;
    constexpr int ACP = MT * 8;

    const int tid = threadIdx.x;
    const int wid = tid >> 5, lane = tid & 31;
    const int wm = wid & 1, wn = wid >> 1;
    const int row0 = blockIdx.y * MT;
    const int col0 = blockIdx.x * 128;
    const int NC = K / KADV;

    float acc[MI][4][4];
    #pragma unroll
    for (int i = 0; i < MI; i++)
        #pragma unroll
        for (int j = 0; j < 4; j++)
            #pragma unroll
            for (int r = 0; r < 4; r++) acc[i][j][r] = 0.f;

    auto load_stage = [&](int c) {
        const int k0 = c * KADV;
        const uint32_t sb = s_base + (uint32_t)((c & 1) * STAGE_BYTES);
        #pragma unroll
        for (int i = tid; i < ACP + 1024; i += 256) {
            const bool isA = i < ACP;
            const int e = isA ? i : i - ACP;
            const int row = e >> 3, ch = e & 7;
            const int grow = (isA ? row0 : col0) + row;
            const __half* src;
            if (NPROD == 3) {
                const int o2 = ch >> 2, kc = ch & 3;
                const __half* base = isA ? (o2 ? op.Alo : op.Ahi) : (o2 ? op.Blo : op.Bhi);
                src = base + (size_t)grow * K + k0 + kc * 8;
            } else {
                src = (isA ? op.Ahi : op.Bhi) + (size_t)grow * K + k0 + ch * 8;
            }
            const uint32_t dst = sb + (uint32_t)((isA ? 0 : MT * 128)
                               + row * 128 + ((ch ^ (row & 7)) << 4));
            CP_ASYNC16(dst, src);
        }
        CP_COMMIT();
    };

    load_stage(0);

    for (int c = 0; c < NC; c++) {
        if (c + 1 < NC) { load_stage(c + 1); CP_WAIT(1); }
        else            { CP_WAIT(0); }
        __syncthreads();

        const uint32_t sA = s_base + (uint32_t)((c & 1) * STAGE_BYTES);
        const uint32_t sB = sA + MT * 128;
        constexpr int NK = (NPROD == 3) ? 2 : 4;

        #pragma unroll
        for (int s = 0; s < NK; s++) {
            uint32_t ah[MI][4], bh[2][4];
            #pragma unroll
            for (int mt = 0; mt < MI; mt++) {
                const int row = wm * (MT / 2) + mt * 16 + (lane & 15);
                const int ch = s * 2 + (lane >> 4);
                ldm_x4(ah[mt], sA + row * 128 + ((ch ^ (row & 7)) << 4));
            }
            #pragma unroll
            for (int ntp = 0; ntp < 2; ntp++) {
                const int row = wn * 32 + ntp * 16 + ((lane >> 4) << 3) + (lane & 7);
                const int ch = s * 2 + ((lane >> 3) & 1);
                ldm_x4(bh[ntp], sB + row * 128 + ((ch ^ (row & 7)) << 4));
            }
            if (NPROD == 3) {
                uint32_t al[MI][4], bl[2][4];
                #pragma unroll
                for (int mt = 0; mt < MI; mt++) {
                    const int row = wm * (MT / 2) + mt * 16 + (lane & 15);
                    const int ch = 4 + s * 2 + (lane >> 4);
                    ldm_x4(al[mt], sA + row * 128 + ((ch ^ (row & 7)) << 4));
                }
                #pragma unroll
                for (int ntp = 0; ntp < 2; ntp++) {
                    const int row = wn * 32 + ntp * 16 + ((lane >> 4) << 3) + (lane & 7);
                    const int ch = 4 + s * 2 + ((lane >> 3) & 1);
                    ldm_x4(bl[ntp], sB + row * 128 + ((ch ^ (row & 7)) << 4));
                }
                #pragma unroll
                for (int mt = 0; mt < MI; mt++)
                    #pragma unroll
                    for (int nt = 0; nt < 4; nt++) {
                        const int p = nt >> 1, q = (nt & 1) * 2;
                        mma16816(acc[mt][nt], ah[mt], bh[p][q], bh[p][q + 1]);
                        mma16816(acc[mt][nt], ah[mt], bl[p][q], bl[p][q + 1]);
                        mma16816(acc[mt][nt], al[mt], bh[p][q], bh[p][q + 1]);
                    }
            } else {
                #pragma unroll
                for (int mt = 0; mt < MI; mt++)
                    #pragma unroll
                    for (int nt = 0; nt < 4; nt++) {
                        const int p = nt >> 1, q = (nt & 1) * 2;
                        mma16816(acc[mt][nt], ah[mt], bh[p][q], bh[p][q + 1]);
                    }
            }
        }
        __syncthreads();
    }

    float csum[4][2];
    if (SEG) {
        #pragma unroll
        for (int nt = 0; nt < 4; nt++) { csum[nt][0] = 0.f; csum[nt][1] = 0.f; }
    }
    #pragma unroll
    for (int mt = 0; mt < MI; mt++) {
        #pragma unroll
        for (int nt = 0; nt < 4; nt++) {
            const int col = col0 + wn * 32 + nt * 8 + (lane & 3) * 2;
            const float2 bv = *reinterpret_cast<const float2*>(op.bias + col);
            #pragma unroll
            for (int half = 0; half < 2; half++) {
                const int grow = row0 + wm * (MT / 2) + mt * 16 + (lane >> 2) + half * 8;
                float v0 = acc[mt][nt][half * 2 + 0] + bv.x;
                float v1 = acc[mt][nt][half * 2 + 1] + bv.y;
                if (BADD) {
                    const float2 bsv = *reinterpret_cast<const float2*>(
                        op.base + (size_t)(grow >> 7) * 3072 + col);
                    v0 += bsv.x; v1 += bsv.y;
                }
                if (RELU) { v0 = fmaxf(v0, 0.f); v1 = fmaxf(v1, 0.f); }
                if (SEG) { csum[nt][0] += v0; csum[nt][1] += v1; }
                if (F32OUT)
                    *reinterpret_cast<float2*>(op.C + (size_t)grow * op.ldc + col) =
                        make_float2(v0, v1);
                if (SPLITOUT) {
                    const __half h0 = __float2half_rn(v0);
                    const __half h1 = __float2half_rn(v1);
                    const __half l0 = __float2half_rn(v0 - __half2float(h0));
                    const __half l1 = __float2half_rn(v1 - __half2float(h1));
                    *reinterpret_cast<__half2*>(op.Chi + (size_t)grow * op.ldc + col) =
                        make_half2(h0, h1);
                    *reinterpret_cast<__half2*>(op.Clo + (size_t)grow * op.ldc + col) =
                        make_half2(l0, l1);
                }
            }
        }
    }
    if (SEG) {
        #pragma unroll
        for (int o = 4; o <= 16; o <<= 1)
            #pragma unroll
            for (int nt = 0; nt < 4; nt++) {
                csum[nt][0] += __shfl_xor_sync(0xffffffffu, csum[nt][0], o);
                csum[nt][1] += __shfl_xor_sync(0xffffffffu, csum[nt][1], o);
            }
        float* scol = reinterpret_cast<float*>(smem);
        if (tid < 128) scol[tid] = 0.f;
        __syncthreads();
        if ((lane >> 2) == 0) {
            #pragma unroll
            for (int nt = 0; nt < 4; nt++) {
                atomicAdd(&scol[wn * 32 + nt * 8 + (lane & 3) * 2 + 0], csum[nt][0]);
                atomicAdd(&scol[wn * 32 + nt * 8 + (lane & 3) * 2 + 1], csum[nt][1]);
            }
        }
        __syncthreads();
        if (tid < 128)
            op.C[(size_t)blockIdx.y * 768 + col0 + tid] = scol[tid] * (1.f / 128.f);
    }
}

// ==================== conversion kernels ====================
__global__ void k_half(const float* __restrict__ in, __half* __restrict__ hi, int n4) {
    int i = blockIdx.x * 256 + threadIdx.x;
    if (i >= n4) return;
    float4 v = reinterpret_cast<const float4*>(in)[i];
    reinterpret_cast<__half2*>(hi)[i * 2 + 0] =
        make_half2(__float2half_rn(v.x), __float2half_rn(v.y));
    reinterpret_cast<__half2*>(hi)[i * 2 + 1] =
        make_half2(__float2half_rn(v.z), __float2half_rn(v.w));
}

struct Split2 { const float* in[2]; __half* hi[2]; __half* lo[2]; int n4[2]; };
__global__ void k_split2(Split2 p) {
    const int z = blockIdx.z;
    int i = blockIdx.x * 256 + threadIdx.x;
    if (i >= p.n4[z]) return;
    float4 v = reinterpret_cast<const float4*>(p.in[z])[i];
    __half h0 = __float2half_rn(v.x), h1 = __float2half_rn(v.y);
    __half h2 = __float2half_rn(v.z), h3 = __float2half_rn(v.w);
    __half l0 = __float2half_rn(v.x - __half2float(h0));
    __half l1 = __float2half_rn(v.y - __half2float(h1));
    __half l2 = __float2half_rn(v.z - __half2float(h2));
    __half l3 = __float2half_rn(v.w - __half2float(h3));
    reinterpret_cast<__half2*>(p.hi[z])[i * 2 + 0] = make_half2(h0, h1);
    reinterpret_cast<__half2*>(p.hi[z])[i * 2 + 1] = make_half2(h2, h3);
    reinterpret_cast<__half2*>(p.lo[z])[i * 2 + 0] = make_half2(l0, l1);
    reinterpret_cast<__half2*>(p.lo[z])[i * 2 + 1] = make_half2(l2, l3);
}

__global__ void k_splitT(const float* __restrict__ W, __half* __restrict__ hi,
                         __half* __restrict__ lo, int K, int N) {
    __shared__ float t[32][33];
    const int kb = blockIdx.y * 32, nb = blockIdx.x * 32;
    const int tx = threadIdx.x & 31, ty = threadIdx.x >> 5;
    #pragma unroll
    for (int r = ty; r < 32; r += 8)
        t[r][tx] = W[(size_t)(kb + r) * N + nb + tx];
    __syncthreads();
    #pragma unroll
    for (int r = ty; r < 32; r += 8) {
        float v = t[tx][r];
        __half h = __float2half_rn(v);
        __half l = __float2half_rn(v - __half2float(h));
        size_t o = (size_t)(nb + r) * K + kb + tx;
        hi[o] = h;
        lo[o] = l;
    }
}

struct ST4 { const float* W[4]; __half* hi[4]; __half* lo[4]; };
__global__ void k_splitT4(ST4 p) {
    const int z = blockIdx.z;
    __shared__ float t[32][33];
    const int kb = blockIdx.y * 32, nb = blockIdx.x * 32;
    const int tx = threadIdx.x & 31, ty = threadIdx.x >> 5;
    #pragma unroll
    for (int r = ty; r < 32; r += 8)
        t[r][tx] = p.W[z][(size_t)(kb + r) * 768 + nb + tx];
    __syncthreads();
    #pragma unroll
    for (int r = ty; r < 32; r += 8) {
        float v = t[tx][r];
        __half h = __float2half_rn(v);
        __half l = __float2half_rn(v - __half2float(h));
        size_t o = (size_t)(nb + r) * 768 + kb + tx;
        p.hi[z][o] = h;
        p.lo[z][o] = l;
    }
}

// ==================== fp32 helper kernels ====================
__global__ void k_softmax_init(const float* __restrict__ scores,
                               const float* __restrict__ state0) {
    int tid = threadIdx.x;
    int warp = tid >> 5, lane = tid & 31;
    if (warp < 8) {
        float v = (lane < 16) ? scores[warp * 16 + lane] : -1e30f;
        float m = v;
        #pragma unroll
        for (int o = 16; o > 0; o >>= 1) m = fmaxf(m, __shfl_xor_sync(0xffffffffu, m, o));
        float e = (lane < 16) ? expf(v - m) : 0.f;
        float s = e;
        #pragma unroll
        for (int o = 16; o > 0; o >>= 1) s += __shfl_xor_sync(0xffffffffu, s, o);
        if (lane < 16) g_ps[warp * 16 + lane] = e / s;
    }
    for (int i = tid; i < 8 * 768; i += blockDim.x) g_h[i] = state0[i % 768];
    for (int i = tid; i < 3072; i += blockDim.x) g_zero[i] = 0.f;
}

template <bool RELU>
__global__ void __launch_bounds__(256) k_gemm16(
    const float* __restrict__ A, const float* __restrict__ W,
    const float* __restrict__ bias, float* __restrict__ C,
    int M, int N, int K) {
    __shared__ __align__(16) float As[32][16];
    __shared__ __align__(16) float Ws[32][128];
    const int tid = threadIdx.x;
    const int row0 = blockIdx.y * 16;
    const int col0 = blockIdx.x * 128;
    const int row = tid >> 4;
    const int cg = tid & 15;
    float acc[8];
    #pragma unroll
    for (int j = 0; j < 8; j++) acc[j] = 0.f;
    for (int k0 = 0; k0 < K; k0 += 32) {
        if (tid < 128) {
            int ar = tid >> 3, ac = (tid & 7) * 4;
            float4 av = make_float4(0.f, 0.f, 0.f, 0.f);
            int gr = row0 + ar;
            if (gr < M) av = *reinterpret_cast<const float4*>(A + (size_t)gr * K + k0 + ac);
            As[ac + 0][ar] = av.x; As[ac + 1][ar] = av.y;
            As[ac + 2][ar] = av.z; As[ac + 3][ar] = av.w;
        }
        #pragma unroll
        for (int j = 0; j < 4; j++) {
            int wr = (tid >> 5) + j * 8;
            int wc = (tid & 31) * 4;
            float4 wv = *reinterpret_cast<const float4*>(W + (size_t)(k0 + wr) * N + col0 + wc);
            *reinterpret_cast<float4*>(&Ws[wr][wc]) = wv;
        }
        __syncthreads();
        #pragma unroll
        for (int k = 0; k < 32; k++) {
            float a = As[k][row];
            float4 b0 = *reinterpret_cast<const float4*>(&Ws[k][cg * 4]);
            float4 b1 = *reinterpret_cast<const float4*>(&Ws[k][64 + cg * 4]);
            acc[0] = fmaf(a, b0.x, acc[0]); acc[1] = fmaf(a, b0.y, acc[1]);
            acc[2] = fmaf(a, b0.z, acc[2]); acc[3] = fmaf(a, b0.w, acc[3]);
            acc[4] = fmaf(a, b1.x, acc[4]); acc[5] = fmaf(a, b1.y, acc[5]);
            acc[6] = fmaf(a, b1.z, acc[6]); acc[7] = fmaf(a, b1.w, acc[7]);
        }
        __syncthreads();
    }
    int r = row0 + row;
    if (r < M) {
        float4 bv0 = *reinterpret_cast<const float4*>(bias + col0 + cg * 4);
        float4 bv1 = *reinterpret_cast<const float4*>(bias + col0 + 64 + cg * 4);
        float o[8];
        o[0] = acc[0] + bv0.x; o[1] = acc[1] + bv0.y;
        o[2] = acc[2] + bv0.z; o[3] = acc[3] + bv0.w;
        o[4] = acc[4] + bv1.x; o[5] = acc[5] + bv1.y;
        o[6] = acc[6] + bv1.z; o[7] = acc[7] + bv1.w;
        if (RELU) {
            #pragma unroll
            for (int j = 0; j < 8; j++) o[j] = fmaxf(o[j], 0.f);
        }
        *reinterpret_cast<float4*>(C + (size_t)r * N + col0 + cg * 4) =
            make_float4(o[0], o[1], o[2], o[3]);
        *reinterpret_cast<float4*>(C + (size_t)r * N + col0 + 64 + cg * 4) =
            make_float4(o[4], o[5], o[6], o[7]);
    }
}

struct G16 { const float* A; const float* W; const float* bias; float* C; int M; int ldc; };
struct G16x3 { G16 g[3]; };
template <bool RELU>
__global__ void __launch_bounds__(256) k_gemm16z(G16x3 p, int N, int K) {
    const G16 gz = p.g[blockIdx.z];
    const int row0 = blockIdx.y * 16;
    if (row0 >= gz.M) return;
    __shared__ __align__(16) float As[32][16];
    __shared__ __align__(16) float Ws[32][128];
    const int tid = threadIdx.x;
    const int col0 = blockIdx.x * 128;
    const int row = tid >> 4;
    const int cg = tid & 15;
    float acc[8];
    #pragma unroll
    for (int j = 0; j < 8; j++) acc[j] = 0.f;
    for (int k0 = 0; k0 < K; k0 += 32) {
        if (tid < 128) {
            int ar = tid >> 3, ac = (tid & 7) * 4;
            float4 av = make_float4(0.f, 0.f, 0.f, 0.f);
            int gr = row0 + ar;
            if (gr < gz.M) av = *reinterpret_cast<const float4*>(gz.A + (size_t)gr * K + k0 + ac);
            As[ac + 0][ar] = av.x; As[ac + 1][ar] = av.y;
            As[ac + 2][ar] = av.z; As[ac + 3][ar] = av.w;
        }
        #pragma unroll
        for (int j = 0; j < 4; j++) {
            int wr = (tid >> 5) + j * 8;
            int wc = (tid & 31) * 4;
            float4 wv = *reinterpret_cast<const float4*>(gz.W + (size_t)(k0 + wr) * N + col0 + wc);
            *reinterpret_cast<float4*>(&Ws[wr][wc]) = wv;
        }
        __syncthreads();
        #pragma unroll
        for (int k = 0; k < 32; k++) {
            float a = As[k][row];
            float4 b0 = *reinterpret_cast<const float4*>(&Ws[k][cg * 4]);
            float4 b1 = *reinterpret_cast<const float4*>(&Ws[k][64 + cg * 4]);
            acc[0] = fmaf(a, b0.x, acc[0]); acc[1] = fmaf(a, b0.y, acc[1]);
            acc[2] = fmaf(a, b0.z, acc[2]); acc[3] = fmaf(a, b0.w, acc[3]);
            acc[4] = fmaf(a, b1.x, acc[4]); acc[5] = fmaf(a, b1.y, acc[5]);
            acc[6] = fmaf(a, b1.z, acc[6]); acc[7] = fmaf(a, b1.w, acc[7]);
        }
        __syncthreads();
    }
    int r = row0 + row;
    if (r < gz.M) {
        float4 bv0 = *reinterpret_cast<const float4*>(gz.bias + col0 + cg * 4);
        float4 bv1 = *reinterpret_cast<const float4*>(gz.bias + col0 + 64 + cg * 4);
        float o[8];
        o[0] = acc[0] + bv0.x; o[1] = acc[1] + bv0.y;
        o[2] = acc[2] + bv0.z; o[3] = acc[3] + bv0.w;
        o[4] = acc[4] + bv1.x; o[5] = acc[5] + bv1.y;
        o[6] = acc[6] + bv1.z; o[7] = acc[7] + bv1.w;
        if (RELU) {
            #pragma unroll
            for (int j = 0; j < 8; j++) o[j] = fmaxf(o[j], 0.f);
        }
        *reinterpret_cast<float4*>(gz.C + (size_t)r * gz.ldc + col0 + cg * 4) =
            make_float4(o[0], o[1], o[2], o[3]);
        *reinterpret_cast<float4*>(gz.C + (size_t)r * gz.ldc + col0 + 64 + cg * 4) =
            make_float4(o[4], o[5], o[6], o[7]);
    }
}

__global__ void k_wsum2() {
    const int z = blockIdx.z;
    const int b = blockIdx.y;
    const int d = blockIdx.x * 256 + threadIdx.x;
    const float* in = (z == 0) ? g_segmean : g_para_h;
    float* outp = (z == 0) ? g_vpre : g_prh;
    float acc = 0.f;
    #pragma unroll
    for (int p = 0; p < 16; p++)
        acc = fmaf(g_ps[b * 16 + p], in[(size_t)(b * 16 + p) * 768 + d], acc);
    outp[b * 768 + d] = acc;
}

__global__ void __launch_bounds__(128) k_gh(const float* __restrict__ whh,
                                            const float* __restrict__ bhh) {
    __shared__ float hs[8 * 768];
    for (int i = threadIdx.x; i < 8 * 768; i += 128) hs[i] = g_h[i];
    __syncthreads();
    int n = blockIdx.x * 128 + threadIdx.x;
    float bv = bhh[n];
    float acc[8];
    #pragma unroll
    for (int b = 0; b < 8; b++) acc[b] = bv;
    const float4* wr = reinterpret_cast<const float4*>(whh + (size_t)n * 768);
    #pragma unroll 4
    for (int k4 = 0; k4 < 192; k4++) {
        float4 w = wr[k4];
        int kb = k4 * 4;
        #pragma unroll
        for (int b = 0; b < 8; b++) {
            const float* hb = hs + b * 768 + kb;
            acc[b] = fmaf(w.x, hb[0], fmaf(w.y, hb[1], fmaf(w.z, hb[2], fmaf(w.w, hb[3], acc[b]))));
        }
    }
    #pragma unroll
    for (int b = 0; b < 8; b++) g_gh[b * 2304 + n] = acc[b];
}

// ==================== fused scan step 1 ====================
__global__ void __launch_bounds__(256) k_step1(
    int s, const float* __restrict__ w1, const float* __restrict__ b1,
    const float* __restrict__ w2)
{
    extern __shared__ float dsm[];
    float* st = dsm;
    float* Ws = dsm + 16 * 768;
    const int tid = threadIdx.x;
    const int row0 = blockIdx.y * 16;
    const int col0 = blockIdx.x * 128;

    for (int idx = tid; idx < 16 * 768; idx += 256) {
        const int rr = idx / 768, hh = idx - rr * 768;
        const int r = row0 + rr;
        const int b = r >> 4, a = r & 15;
        const size_t gib = (size_t)((b * 8 + s) * 16 + a) * 2304;
        const float* ghrow;
        const float* hprev;
        if (s == 0) {
            ghrow = g_gh + b * 2304;
            hprev = g_h + b * 768;
        } else {
            const int prev = (b * 8 + (s - 1)) * 16 + g_best[b];
            ghrow = g_ghall + (size_t)prev * 2304;
            hprev = g_x + (size_t)prev * 768;
        }
        const float ir = g_gi[gib + hh];
        const float iz = g_gi[gib + 768 + hh];
        const float in_ = g_gi[gib + 1536 + hh];
        const float rr_ = 1.f / (1.f + expf(-(ir + ghrow[hh])));
        const float zz = 1.f / (1.f + expf(-(iz + ghrow[768 + hh])));
        const float nn = tanhf(in_ + rr_ * ghrow[1536 + hh]);
        st[rr * 768 + hh] = (1.f - zz) * nn + zz * hprev[hh];
    }
    __syncthreads();

    const int row = tid >> 4, cg = tid & 15;
    float acc[8];
    #pragma unroll
    for (int j = 0; j < 8; j++) acc[j] = 0.f;
    for (int k0 = 0; k0 < 768; k0 += 32) {
        #pragma unroll
        for (int j = 0; j < 4; j++) {
            const int wr = (tid >> 5) + j * 8;
            const int wc = (tid & 31) * 4;
            *reinterpret_cast<float4*>(&Ws[wr * 128 + wc]) =
                *reinterpret_cast<const float4*>(w1 + (size_t)(k0 + wr) * 768 + col0 + wc);
        }
        __syncthreads();
        #pragma unroll
        for (int k = 0; k < 32; k++) {
            const float a = st[row * 768 + k0 + k];
            const float4 b0 = *reinterpret_cast<const float4*>(&Ws[k * 128 + cg * 4]);
            const float4 b1v = *reinterpret_cast<const float4*>(&Ws[k * 128 + 64 + cg * 4]);
            acc[0] = fmaf(a, b0.x, acc[0]); acc[1] = fmaf(a, b0.y, acc[1]);
            acc[2] = fmaf(a, b0.z, acc[2]); acc[3] = fmaf(a, b0.w, acc[3]);
            acc[4] = fmaf(a, b1v.x, acc[4]); acc[5] = fmaf(a, b1v.y, acc[5]);
            acc[6] = fmaf(a, b1v.z, acc[6]); acc[7] = fmaf(a, b1v.w, acc[7]);
        }
        __syncthreads();
    }

    const float4 bv0 = *reinterpret_cast<const float4*>(b1 + col0 + cg * 4);
    const float4 bv1 = *reinterpret_cast<const float4*>(b1 + col0 + 64 + cg * 4);
    const float4 w20 = *reinterpret_cast<const float4*>(w2 + col0 + cg * 4);
    const float4 w21 = *reinterpret_cast<const float4*>(w2 + col0 + 64 + cg * 4);
    float part = 0.f;
    part += fmaxf(acc[0] + bv0.x, 0.f) * w20.x;
    part += fmaxf(acc[1] + bv0.y, 0.f) * w20.y;
    part += fmaxf(acc[2] + bv0.z, 0.f) * w20.z;
    part += fmaxf(acc[3] + bv0.w, 0.f) * w20.w;
    part += fmaxf(acc[4] + bv1.x, 0.f) * w21.x;
    part += fmaxf(acc[5] + bv1.y, 0.f) * w21.y;
    part += fmaxf(acc[6] + bv1.z, 0.f) * w21.z;
    part += fmaxf(acc[7] + bv1.w, 0.f) * w21.w;
    #pragma unroll
    for (int off = 1; off < 16; off <<= 1)
        part += __shfl_xor_sync(0xffffffffu, part, off);
    if (cg == 0)
        g_logpart[blockIdx.x * 128 + row0 + row] = part;
}

__global__ void k_step2(const float* __restrict__ b2, float* __restrict__ out, int s) {
    const int b = blockIdx.x;
    const int lane = threadIdx.x;
    float val = -1e30f;
    int idx = 1000;
    if (lane < 16) {
        float lg = b2[0];
        #pragma unroll
        for (int x = 0; x < 6; x++) lg += g_logpart[x * 128 + b * 16 + lane];
        out[(b * 8 + s) * 16 + lane] = lg;
        val = lg;
        idx = lane;
    }
    #pragma unroll
    for (int off = 8; off > 0; off >>= 1) {
        const float oval = __shfl_down_sync(0xffffffffu, val, off);
        const int oidx = __shfl_down_sync(0xffffffffu, idx, off);
        if (oval > val || (oval == val && oidx < idx)) { val = oval; idx = oidx; }
    }
    if (lane == 0) g_best[b] = idx;
}

// ==================== host ====================
#define GETSYM(p, s) cudaGetSymbolAddress((void**)&(p), s)

extern "C" void kernel_launch(void* const* d_in, const int* in_sizes, int n_in,
                              void* d_out, int out_size) {
    (void)in_sizes; (void)n_in; (void)out_size;
    const float* video     = (const float*)d_in[0];
    const float* para      = (const float*)d_in[1];
    const float* question  = (const float*)d_in[2];
    const float* pscore    = (const float*)d_in[3];
    const float* a_texts   = (const float*)d_in[4];
    const float* a_buttons = (const float*)d_in[5];
    const float* mv_w1 = (const float*)d_in[6],  *mv_b1 = (const float*)d_in[7];
    const float* mv_w2 = (const float*)d_in[8],  *mv_b2 = (const float*)d_in[9];
    const float* mt_w1 = (const float*)d_in[10], *mt_b1 = (const float*)d_in[11];
    const float* mt_w2 = (const float*)d_in[12], *mt_b2 = (const float*)d_in[13];
    const float* mp_w1 = (const float*)d_in[14], *mp_b1 = (const float*)d_in[15];
    const float* mp_w2 = (const float*)d_in[16], *mp_b2 = (const float*)d_in[17];
    const float* wih   = (const float*)d_in[18], *bih   = (const float*)d_in[19];
    const float* whh   = (const float*)d_in[20], *bhh   = (const float*)d_in[21];
    const float* pr_w1 = (const float*)d_in[22], *pr_b1 = (const float*)d_in[23];
    const float* pr_w2 = (const float*)d_in[24], *pr_b2 = (const float*)d_in[25];
    const float* state0 = (const float*)d_in[26];
    float* out = (float*)d_out;

    float *pseg, *pparah, *pqh, *pvpre, *pprh;
    float *pvpq, *pzero, *pbase, *px, *pgi, *pghall;
    GETSYM(pseg, g_segmean); GETSYM(pparah, g_para_h); GETSYM(pqh, g_qh);
    GETSYM(pvpre, g_vpre); GETSYM(pprh, g_prh);
    GETSYM(pvpq, g_vpq); GETSYM(pzero, g_zero); GETSYM(pbase, g_base);
    GETSYM(px, g_x); GETSYM(pgi, g_gi); GETSYM(pghall, g_ghall);

    __half *vid_hi, *atx_hi, *atx_lo, *abt_hi, *abt_lo;
    __half *wih_hi, *wih_lo, *whh_hi, *whh_lo;
    __half *mvw1t_hi, *mvw1t_lo, *mvw2t_hi, *mvw2t_lo, *mtw1t_hi, *mtw1t_lo;
    __half *mtw2t_hi, *mtw2t_lo, *mpw1rt_hi, *mpw1rt_lo, *mpw2t_hi, *mpw2t_lo;
    __half *tha_hi, *tha_lo, *thb_hi, *thb_lo, *inpAB_hi, *inpAB_lo;
    __half *preh_hi, *preh_lo, *x_hi, *x_lo;
    GETSYM(vid_hi, g_vid_hi);
    GETSYM(atx_hi, g_atx_hi); GETSYM(atx_lo, g_atx_lo);
    GETSYM(abt_hi, g_abt_hi); GETSYM(abt_lo, g_abt_lo);
    GETSYM(wih_hi, g_wih_hi); GETSYM(wih_lo, g_wih_lo);
    GETSYM(whh_hi, g_whh_hi); GETSYM(whh_lo, g_whh_lo);
    GETSYM(mvw1t_hi, g_mvw1t_hi); GETSYM(mvw1t_lo, g_mvw1t_lo);
    GETSYM(mvw2t_hi, g_mvw2t_hi); GETSYM(mvw2t_lo, g_mvw2t_lo);
    GETSYM(mtw1t_hi, g_mtw1t_hi); GETSYM(mtw1t_lo, g_mtw1t_lo);
    GETSYM(mtw2t_hi, g_mtw2t_hi); GETSYM(mtw2t_lo, g_mtw2t_lo);
    GETSYM(mpw1rt_hi, g_mpw1rt_hi); GETSYM(mpw1rt_lo, g_mpw1rt_lo);
    GETSYM(mpw2t_hi, g_mpw2t_hi); GETSYM(mpw2t_lo, g_mpw2t_lo);
    GETSYM(tha_hi, g_tha_hi); GETSYM(tha_lo, g_tha_lo);
    GETSYM(thb_hi, g_thb_hi); GETSYM(thb_lo, g_thb_lo);
    GETSYM(inpAB_hi, g_inpAB_hi); GETSYM(inpAB_lo, g_inpAB_lo);
    GETSYM(preh_hi, g_preh_hi); GETSYM(preh_lo, g_preh_lo);
    GETSYM(x_hi, g_x_hi); GETSYM(x_lo, g_x_lo);

    constexpr int SM128 = (128 + 128) * 128 * 2;
    constexpr int SM64  = (64 + 128) * 128 * 2;
    constexpr int SM32  = (32 + 128) * 128 * 2;
    constexpr int SMSTEP = 16 * 768 * 4 + 32 * 128 * 4;
    cudaFuncSetAttribute(k_hmma<128, 1, true,  false, false, false, true >, cudaFuncAttributeMaxDynamicSharedMemorySize, SM128);
    cudaFuncSetAttribute(k_hmma<32,  3, true,  true,  false, false, false>, cudaFuncAttributeMaxDynamicSharedMemorySize, SM32);
    cudaFuncSetAttribute(k_hmma<32,  3, false, true,  false, false, false>, cudaFuncAttributeMaxDynamicSharedMemorySize, SM32);
    cudaFuncSetAttribute(k_hmma<64,  3, true,  true,  false, true,  false>, cudaFuncAttributeMaxDynamicSharedMemorySize, SM64);
    cudaFuncSetAttribute(k_hmma<32,  3, false, true,  true,  false, false>, cudaFuncAttributeMaxDynamicSharedMemorySize, SM32);
    cudaFuncSetAttribute(k_hmma<64,  3, false, false, true,  false, false>, cudaFuncAttributeMaxDynamicSharedMemorySize, SM64);
    cudaFuncSetAttribute(k_step1, cudaFuncAttributeMaxDynamicSharedMemorySize, SMSTEP);

    auto mk = [](const __half* Ahi, const __half* Alo, const __half* Bhi,
                 const __half* Blo, const float* bias, const float* base,
                 float* C, __half* Chi, __half* Clo, int ldc) {
        Ops o; o.Ahi = Ahi; o.Alo = Alo; o.Bhi = Bhi; o.Blo = Blo;
        o.bias = bias; o.base = base; o.C = C; o.Chi = Chi; o.Clo = Clo;
        o.ldc = ldc; return o;
    };

    cudaStream_t s2, s3;
    cudaEvent_t e0, e1, epq, e3, e4;
    cudaStreamCreateWithFlags(&s2, cudaStreamNonBlocking);
    cudaStreamCreateWithFlags(&s3, cudaStreamNonBlocking);
    cudaEventCreateWithFlags(&e0, cudaEventDisableTiming);
    cudaEventCreateWithFlags(&e1, cudaEventDisableTiming);
    cudaEventCreateWithFlags(&epq, cudaEventDisableTiming);
    cudaEventCreateWithFlags(&e3, cudaEventDisableTiming);
    cudaEventCreateWithFlags(&e4, cudaEventDisableTiming);

    // ---- default: init + 4x weight split (needed by video + a-branch) ----
    k_softmax_init<<<1, 256>>>(pscore, state0);
    cudaEventRecord(e0, 0);
    {
        ST4 p;
        p.W[0] = mv_w1; p.hi[0] = mvw1t_hi; p.lo[0] = mvw1t_lo;
        p.W[1] = mv_w2; p.hi[1] = mvw2t_hi; p.lo[1] = mvw2t_lo;
        p.W[2] = mt_w1; p.hi[2] = mtw1t_hi; p.lo[2] = mtw1t_lo;
        p.W[3] = mt_w2; p.hi[3] = mtw2t_hi; p.lo[3] = mtw2t_lo;
        k_splitT4<<<dim3(24, 24, 4), 256>>>(p);
    }
    cudaEventRecord(e1, 0);

    // ---- s3: para/question L1 + gh + join-only weight splits ----
    cudaStreamWaitEvent(s3, e0, 0);
    {
        G16x3 p;
        p.g[0] = {para,     mt_w1, mt_b1, pparah, 128, 768};
        p.g[1] = {question, mt_w1, mt_b1, pqh,    8,   768};
        p.g[2] = p.g[1];
        k_gemm16z<true><<<dim3(6, 8, 2), 256, 0, s3>>>(p, 768, 768);
    }
    cudaEventRecord(epq, s3);
    k_gh<<<18, 128, 0, s3>>>(whh, bhh);
    k_splitT<<<dim3(96, 48), 256, 0, s3>>>(mp_w1 + (size_t)1536 * 3072, mpw1rt_hi, mpw1rt_lo, 1536, 3072);
    k_splitT<<<dim3(24, 96), 256, 0, s3>>>(mp_w2, mpw2t_hi, mpw2t_lo, 3072, 768);
    {
        Split2 p;
        p.in[0] = wih; p.hi[0] = wih_hi; p.lo[0] = wih_lo; p.n4[0] = 2304 * 768 / 4;
        p.in[1] = whh; p.hi[1] = whh_hi; p.lo[1] = whh_lo; p.n4[1] = 2304 * 768 / 4;
        k_split2<<<dim3((2304 * 768 / 4 + 255) / 256, 1, 2), 256, 0, s3>>>(p);
    }
    cudaEventRecord(e4, s3);

    // ---- s2: video chain ----
    cudaStreamWaitEvent(s2, e0, 0);
    k_half<<<(16384 * 768 / 4 + 255) / 256, 256, 0, s2>>>(video, vid_hi, 16384 * 768 / 4);
    cudaStreamWaitEvent(s2, e1, 0);
    {
        Ops2 o2; o2.o[0] = o2.o[1] = mk(vid_hi, nullptr, mvw1t_hi, nullptr,
                                        mv_b1, nullptr, pseg, nullptr, nullptr, 768);
        k_hmma<128, 1, true, false, false, false, true><<<dim3(6, 128, 1), 256, SM128, s2>>>(o2, 16384, 768, 768);
    }
    cudaStreamWaitEvent(s2, epq, 0);
    k_wsum2<<<dim3(3, 8, 2), 256, 0, s2>>>();
    {
        G16x3 p;
        p.g[0] = {pvpre, mv_w2, mv_b2, pvpq + 0,    8, 2304};
        p.g[1] = {pprh,  mt_w2, mt_b2, pvpq + 768,  8, 2304};
        p.g[2] = {pqh,   mt_w2, mt_b2, pvpq + 1536, 8, 2304};
        k_gemm16z<false><<<dim3(6, 1, 3), 256, 0, s2>>>(p, 768, 768);
    }
    k_gemm16<false><<<dim3(24, 1), 256, 0, s2>>>(pvpq, mp_w1, mp_b1, pbase, 8, 3072, 2304);
    cudaEventRecord(e3, s2);

    // ---- default: a-branch ----
    {
        Split2 p;
        p.in[0] = a_texts;   p.hi[0] = atx_hi; p.lo[0] = atx_lo; p.n4[0] = 1024 * 768 / 4;
        p.in[1] = a_buttons; p.hi[1] = abt_hi; p.lo[1] = abt_lo; p.n4[1] = 1024 * 768 / 4;
        k_split2<<<dim3((1024 * 768 / 4 + 255) / 256, 1, 2), 256>>>(p);
    }
    {
        Ops2 o2;
        o2.o[0] = mk(atx_hi, atx_lo, mtw1t_hi, mtw1t_lo, mt_b1, nullptr,
                     nullptr, tha_hi, tha_lo, 768);
        o2.o[1] = mk(abt_hi, abt_lo, mvw1t_hi, mvw1t_lo, mv_b1, nullptr,
                     nullptr, thb_hi, thb_lo, 768);
        k_hmma<32, 3, true, true, false, false, false><<<dim3(6, 32, 2), 256, SM32>>>(o2, 1024, 768, 768);
    }
    {
        Ops2 o2;
        o2.o[0] = mk(tha_hi, tha_lo, mtw2t_hi, mtw2t_lo, mt_b2, nullptr,
                     nullptr, inpAB_hi, inpAB_lo, 1536);
        o2.o[1] = mk(thb_hi, thb_lo, mvw2t_hi, mvw2t_lo, mv_b2, nullptr,
                     nullptr, inpAB_hi + 768, inpAB_lo + 768, 1536);
        k_hmma<32, 3, false, true, false, false, false><<<dim3(6, 32, 2), 256, SM32>>>(o2, 1024, 768, 768);
    }

    // ---- join: needs base (s2), weight splits + gh (s3), inpAB (default) ----
    cudaStreamWaitEvent(0, e3, 0);
    cudaStreamWaitEvent(0, e4, 0);
    {
        Ops2 o2; o2.o[0] = o2.o[1] = mk(inpAB_hi, inpAB_lo, mpw1rt_hi, mpw1rt_lo,
                                        pzero, pbase, nullptr, preh_hi, preh_lo, 3072);
        k_hmma<64, 3, true, true, false, true, false><<<dim3(24, 16, 1), 256, SM64>>>(o2, 1024, 3072, 1536);
    }
    {
        Ops2 o2; o2.o[0] = o2.o[1] = mk(preh_hi, preh_lo, mpw2t_hi, mpw2t_lo,
                                        mp_b2, nullptr, px, x_hi, x_lo, 768);
        k_hmma<32, 3, false, true, true, false, false><<<dim3(6, 32, 1), 256, SM32>>>(o2, 1024, 768, 3072);
    }
    {
        Ops2 o2;
        o2.o[0] = mk(x_hi, x_lo, wih_hi, wih_lo, bih, nullptr, pgi, nullptr, nullptr, 2304);
        o2.o[1] = mk(x_hi, x_lo, whh_hi, whh_lo, bhh, nullptr, pghall, nullptr, nullptr, 2304);
        k_hmma<64, 3, false, false, true, false, false><<<dim3(18, 16, 2), 256, SM64>>>(o2, 1024, 2304, 768);
    }

    // sequential scan
    for (int s = 0; s < 8; s++) {
        k_step1<<<dim3(6, 8), 256, SMSTEP>>>(s, pr_w1, pr_b1, pr_w2);
        k_step2<<<8, 32>>>(pr_b2, out, s);
    }

    cudaEventDestroy(e0);
    cudaEventDestroy(e1);
    cudaEventDestroy(epq);
    cudaEventDestroy(e3);
    cudaEventDestroy(e4);
    cudaStreamDestroy(s2);
    cudaStreamDestroy(s3);
}